// round 5
// baseline (speedup 1.0000x reference)
#include <cuda_runtime.h>
#include <cuda_bf16.h>
#include <cuda_fp16.h>
#include <cstdint>

// Problem dims
#define BB  256
#define TT  256
#define IND 128
#define SS  1024

// ---------------- scratch (__device__ globals) ------------------------------
__device__ float g_ext[(size_t)TT * BB * SS];            // [t][b][s] fp32
__device__ __half g_sAh[BB * SS], g_sAl[BB * SS];        // state hi/lo fp16
__device__ __half g_sBh[BB * SS], g_sBl[BB * SS];
__device__ __half g_W1[SS * SS], g_W2[SS * SS];          // weights plain fp16
__device__ __nv_bfloat16 g_xh[(size_t)BB * TT * IND], g_xl[(size_t)BB * TT * IND];
__device__ __nv_bfloat16 g_Winh[SS * IND], g_Winl[SS * IND];
__device__ unsigned g_ctr;                               // grid barrier counter

// ---------------- helpers ---------------------------------------------------
__device__ __forceinline__ uint32_t smem_u32(const void* p) {
    uint32_t a;
    asm("{ .reg .u64 t; cvta.to.shared.u64 t, %1; cvt.u32.u64 %0, t; }" : "=r"(a) : "l"(p));
    return a;
}
__device__ __forceinline__ void cp16(uint32_t dst, const void* src) {
    asm volatile("cp.async.cg.shared.global [%0], [%1], 16;" :: "r"(dst), "l"(src));
}
__device__ __forceinline__ void cp_commit() { asm volatile("cp.async.commit_group;"); }
__device__ __forceinline__ void cp_wait0()  { asm volatile("cp.async.wait_group 0;"); }
__device__ __forceinline__ void cp_wait1()  { asm volatile("cp.async.wait_group 1;"); }

__device__ __forceinline__ void mma_bf16(float* c, const uint32_t* a,
                                         uint32_t b0, uint32_t b1) {
    asm volatile(
        "mma.sync.aligned.m16n8k16.row.col.f32.bf16.bf16.f32 "
        "{%0,%1,%2,%3}, {%4,%5,%6,%7}, {%8,%9}, {%0,%1,%2,%3};"
        : "+f"(c[0]), "+f"(c[1]), "+f"(c[2]), "+f"(c[3])
        : "r"(a[0]), "r"(a[1]), "r"(a[2]), "r"(a[3]), "r"(b0), "r"(b1));
}
__device__ __forceinline__ void mma_f16(float* c, const uint32_t* a,
                                        uint32_t b0, uint32_t b1) {
    asm volatile(
        "mma.sync.aligned.m16n8k16.row.col.f32.f16.f16.f32 "
        "{%0,%1,%2,%3}, {%4,%5,%6,%7}, {%8,%9}, {%0,%1,%2,%3};"
        : "+f"(c[0]), "+f"(c[1]), "+f"(c[2]), "+f"(c[3])
        : "r"(a[0]), "r"(a[1]), "r"(a[2]), "r"(a[3]), "r"(b0), "r"(b1));
}
__device__ __forceinline__ void ldsm_x4(uint32_t* r, uint32_t addr) {
    asm volatile("ldmatrix.sync.aligned.m8n8.x4.shared.b16 {%0,%1,%2,%3}, [%4];"
                 : "=r"(r[0]), "=r"(r[1]), "=r"(r[2]), "=r"(r[3]) : "r"(addr));
}

// ---------------- grid barrier (all 128 CTAs co-resident) -------------------
__device__ __forceinline__ void grid_bar(unsigned target) {
    __threadfence();
    __syncthreads();
    if (threadIdx.x == 0) {
        atomicAdd(&g_ctr, 1u);
        while (*((volatile unsigned*)&g_ctr) < target) { }
    }
    __syncthreads();
    __threadfence();
}

__global__ void zero_ctr() { g_ctr = 0; }

// ---------------- persistent scan kernel ------------------------------------
// 256 steps x 2 layers, fp16 2-term: O = relu((Ah+Al) @ W^T + bias) (+ ext)
// CTA tile 32x64, KC=64, 2-stage cp.async, 256 threads, warp tile 16x16.
#define M_TILE 32
#define N_TILE 64
#define KC     64
#define NCHUNK (SS / KC)          // 16
#define A_HI 0
#define A_LO 4096
#define B_W  8192
#define STAGE_BYTES 16384
#define SCAN_SM (2 * STAGE_BYTES)   // 32768 (static)

__device__ __forceinline__ void load_chunk_h(
    uint32_t st, int kc0, int tid, int m0, int n0,
    const __half* __restrict__ Ah, const __half* __restrict__ Al,
    const __half* __restrict__ W)
{
    #pragma unroll
    for (int i = 0; i < 4; i++) {
        int u = tid + (i << 8);              // 0..1023
        const __half* src;
        uint32_t dst;
        if (u < 512) {                       // A hi (0..255), A lo (256..511)
            int sel = u >> 8, v = u & 255;
            int row = v >> 3, cu = v & 7;
            src = (sel ? Al : Ah) + (size_t)(m0 + row) * SS + kc0 + cu * 8;
            dst = st + (sel ? A_LO : A_HI) + row * 128 + ((cu ^ (row & 7)) << 4);
        } else {                             // B (512..1023)
            int v = u - 512;
            int row = v >> 3, cu = v & 7;
            src = W + (size_t)(n0 + row) * SS + kc0 + cu * 8;
            dst = st + B_W + row * 128 + ((cu ^ (row & 7)) << 4);
        }
        cp16(dst, src);
    }
    cp_commit();
}

__device__ __forceinline__ void layer_body(
    uint32_t sb, int tid, int m0, int n0,
    int rowA, int swA, int rowB, int swB, int khalf,
    int wm, int wn, int g, int t4,
    const __half* __restrict__ Ah, const __half* __restrict__ Al,
    const __half* __restrict__ W,
    const float* __restrict__ bias, const float* __restrict__ ext_next,
    __half* __restrict__ Oh, __half* __restrict__ Ol)
{
    const uint32_t aH0 = sb + A_HI + rowA * 128;
    const uint32_t aL0 = sb + A_LO + rowA * 128;
    const uint32_t bW0 = sb + B_W  + rowB * 128;

    float acc[2][4] = {};

    load_chunk_h(sb, 0, tid, m0, n0, Ah, Al, W);

    #pragma unroll 1
    for (int c = 0; c < NCHUNK; c++) {
        if (c + 1 < NCHUNK) {
            load_chunk_h(sb + ((c + 1) & 1) * STAGE_BYTES, (c + 1) * KC,
                         tid, m0, n0, Ah, Al, W);
            cp_wait1();
        } else {
            cp_wait0();
        }
        __syncthreads();

        const uint32_t stg = (c & 1) * STAGE_BYTES;
        #pragma unroll
        for (int ks = 0; ks < 4; ks++) {
            const int u = ks * 2 + khalf;
            uint32_t ah[4], al[4], bw[4];
            ldsm_x4(ah, aH0 + stg + ((u ^ swA) << 4));
            ldsm_x4(al, aL0 + stg + ((u ^ swA) << 4));
            ldsm_x4(bw, bW0 + stg + ((u ^ swB) << 4));
            mma_f16(acc[0], ah, bw[0], bw[2]);
            mma_f16(acc[0], al, bw[0], bw[2]);
            mma_f16(acc[1], ah, bw[1], bw[3]);
            mma_f16(acc[1], al, bw[1], bw[3]);
        }
        __syncthreads();
    }

    // Epilogue: bias + relu (+ ext_next) + fp16 hi/lo split + store
    const int row0 = m0 + wm + g;
    const int row1 = row0 + 8;
    #pragma unroll
    for (int j = 0; j < 2; j++) {
        const int col = n0 + wn + j * 8 + t4 * 2;
        float2 bb = *(const float2*)(bias + col);
        float v00 = fmaxf(acc[j][0] + bb.x, 0.0f);
        float v01 = fmaxf(acc[j][1] + bb.y, 0.0f);
        float v10 = fmaxf(acc[j][2] + bb.x, 0.0f);
        float v11 = fmaxf(acc[j][3] + bb.y, 0.0f);
        if (ext_next) {
            float2 e0 = *(const float2*)(ext_next + (size_t)row0 * SS + col);
            float2 e1 = *(const float2*)(ext_next + (size_t)row1 * SS + col);
            v00 += e0.x; v01 += e0.y; v10 += e1.x; v11 += e1.y;
        }
        __half h00 = __float2half_rn(v00), h01 = __float2half_rn(v01);
        __half h10 = __float2half_rn(v10), h11 = __float2half_rn(v11);
        __half l00 = __float2half_rn(v00 - __half2float(h00));
        __half l01 = __float2half_rn(v01 - __half2float(h01));
        __half l10 = __float2half_rn(v10 - __half2float(h10));
        __half l11 = __float2half_rn(v11 - __half2float(h11));
        *(uint32_t*)(Oh + (size_t)row0 * SS + col) =
            (uint32_t)__half_as_ushort(h00) | ((uint32_t)__half_as_ushort(h01) << 16);
        *(uint32_t*)(Oh + (size_t)row1 * SS + col) =
            (uint32_t)__half_as_ushort(h10) | ((uint32_t)__half_as_ushort(h11) << 16);
        *(uint32_t*)(Ol + (size_t)row0 * SS + col) =
            (uint32_t)__half_as_ushort(l00) | ((uint32_t)__half_as_ushort(l01) << 16);
        *(uint32_t*)(Ol + (size_t)row1 * SS + col) =
            (uint32_t)__half_as_ushort(l10) | ((uint32_t)__half_as_ushort(l11) << 16);
    }
}

__global__ __launch_bounds__(256) void scan_kernel(
    __half* __restrict__ sAh, __half* __restrict__ sAl,
    __half* __restrict__ sBh, __half* __restrict__ sBl,
    const __half* __restrict__ W1, const __half* __restrict__ W2,
    const float* __restrict__ b1, const float* __restrict__ b2,
    const float* __restrict__ ext)
{
    __shared__ char smem[SCAN_SM];
    const uint32_t sb = smem_u32(smem);
    const int tid = threadIdx.x;
    const int wid = tid >> 5, lane = tid & 31;
    const int g = lane >> 2, t4 = lane & 3;
    const int wm = (wid >> 2) << 4;          // 0/16
    const int wn = (wid & 3) << 4;           // 0/16/32/48
    const int m0 = blockIdx.x * M_TILE, n0 = blockIdx.y * N_TILE;

    const int lr = lane & 7;
    const int half8 = (lane >> 3) & 1;
    const int khalf = (lane >> 4) & 1;
    const int rowA = wm + half8 * 8 + lr;
    const int rowB = wn + half8 * 8 + lr;
    const int swA = rowA & 7, swB = rowB & 7;

    unsigned tgt = 128;
    #pragma unroll 1
    for (int t = 0; t < TT; t++) {
        layer_body(sb, tid, m0, n0, rowA, swA, rowB, swB, khalf, wm, wn, g, t4,
                   sAh, sAl, W1, b1, nullptr, sBh, sBl);
        grid_bar(tgt); tgt += 128;
        const float* en = (t + 1 < TT) ? ext + (size_t)(t + 1) * BB * SS : nullptr;
        layer_body(sb, tid, m0, n0, rowA, swA, rowB, swB, khalf, wm, wn, g, t4,
                   sBh, sBl, W2, b2, en, sAh, sAl);
        grid_bar(tgt); tgt += 128;
    }
}

// ---------------- input projection (bf16 3-term MMA, unchanged) -------------
#define PA_HI 0
#define PA_LO 16384
#define PB_HI 32768
#define PB_LO 49152
#define P_SM  65536

__global__ __launch_bounds__(256) void proj_mma(
    const __nv_bfloat16* __restrict__ Xh, const __nv_bfloat16* __restrict__ Xl,
    const __nv_bfloat16* __restrict__ Wh, const __nv_bfloat16* __restrict__ Wl,
    const float* __restrict__ bias, float* __restrict__ Out)
{
    extern __shared__ char smem[];
    const uint32_t sb = smem_u32(smem);
    const int tid = threadIdx.x;
    const int wid = tid >> 5, lane = tid & 31;
    const int g = lane >> 2, t4 = lane & 3;
    const int wm = (wid >> 1) << 4;          // 0..48
    const int wn = (wid & 1) << 5;           // 0/32
    const int m0 = blockIdx.x * 64, n0 = blockIdx.y * 64;

    #pragma unroll
    for (int i = 0; i < 16; i++) {
        int u = tid + (i << 8);              // 0..4095
        const __nv_bfloat16* src;
        uint32_t dst;
        if (u < 2048) {
            int sel = u >> 10, v = u & 1023;
            int row = v >> 4, cu = v & 15;
            src = (sel ? Xl : Xh) + (size_t)(m0 + row) * IND + cu * 8;
            dst = sb + (sel ? PA_LO : PA_HI) + row * 256
                + (((cu & 8) | ((cu & 7) ^ (row & 7))) << 4);
        } else {
            int w = u - 2048;
            int sel = w >> 10, v = w & 1023;
            int row = v >> 4, cu = v & 15;
            src = (sel ? Wl : Wh) + (size_t)(n0 + row) * IND + cu * 8;
            dst = sb + (sel ? PB_LO : PB_HI) + row * 256
                + (((cu & 8) | ((cu & 7) ^ (row & 7))) << 4);
        }
        cp16(dst, src);
    }
    cp_commit();
    cp_wait0();
    __syncthreads();

    const int lr = lane & 7;
    const int half8 = (lane >> 3) & 1;
    const int khalf = (lane >> 4) & 1;
    const int rowA = wm + half8 * 8 + lr;
    const int rowB = wn + half8 * 8 + lr;
    const int swA = rowA & 7, swB = rowB & 7;

    float acc[4][4] = {};
    #pragma unroll
    for (int ks = 0; ks < 8; ks++) {
        const int u = ks * 2 + khalf;
        const uint32_t puA = (((u & 8) | ((u & 7) ^ swA)) << 4);
        const uint32_t puB = (((u & 8) | ((u & 7) ^ swB)) << 4);
        uint32_t ah[4], al[4];
        ldsm_x4(ah, sb + PA_HI + rowA * 256 + puA);
        ldsm_x4(al, sb + PA_LO + rowA * 256 + puA);
        #pragma unroll
        for (int jj = 0; jj < 2; jj++) {
            uint32_t bh[4], bl[4];
            ldsm_x4(bh, sb + PB_HI + (rowB + jj * 16) * 256 + puB);
            ldsm_x4(bl, sb + PB_LO + (rowB + jj * 16) * 256 + puB);
            mma_bf16(acc[jj * 2],     ah, bh[0], bh[2]);
            mma_bf16(acc[jj * 2],     ah, bl[0], bl[2]);
            mma_bf16(acc[jj * 2],     al, bh[0], bh[2]);
            mma_bf16(acc[jj * 2 + 1], ah, bh[1], bh[3]);
            mma_bf16(acc[jj * 2 + 1], ah, bl[1], bl[3]);
            mma_bf16(acc[jj * 2 + 1], al, bh[1], bh[3]);
        }
    }

    const int r0 = m0 + wm + g;
    const int r1 = r0 + 8;
    const int b0r = r0 >> 8, t0r = r0 & 255;
    const int b1r = r1 >> 8, t1r = r1 & 255;
    #pragma unroll
    for (int j = 0; j < 4; j++) {
        const int col = n0 + wn + j * 8 + t4 * 2;
        float2 bb = *(const float2*)(bias + col);
        float2 o0 = make_float2(acc[j][0] + bb.x, acc[j][1] + bb.y);
        float2 o1 = make_float2(acc[j][2] + bb.x, acc[j][3] + bb.y);
        *(float2*)(Out + ((size_t)t0r * BB + b0r) * SS + col) = o0;
        *(float2*)(Out + ((size_t)t1r * BB + b1r) * SS + col) = o1;
    }
}

// ---------------- conversion kernels ----------------------------------------
__global__ void splitBF_kernel(const float4* __restrict__ in,
                               uint2* __restrict__ hi, uint2* __restrict__ lo, int n4)
{
    int i = blockIdx.x * blockDim.x + threadIdx.x;
    if (i >= n4) return;
    float4 v = in[i];
    __nv_bfloat16 h0 = __float2bfloat16(v.x), h1 = __float2bfloat16(v.y);
    __nv_bfloat16 h2 = __float2bfloat16(v.z), h3 = __float2bfloat16(v.w);
    __nv_bfloat16 l0 = __float2bfloat16(v.x - __bfloat162float(h0));
    __nv_bfloat16 l1 = __float2bfloat16(v.y - __bfloat162float(h1));
    __nv_bfloat16 l2 = __float2bfloat16(v.z - __bfloat162float(h2));
    __nv_bfloat16 l3 = __float2bfloat16(v.w - __bfloat162float(h3));
    uint2 H, L;
    H.x = (uint32_t)__bfloat16_as_ushort(h0) | ((uint32_t)__bfloat16_as_ushort(h1) << 16);
    H.y = (uint32_t)__bfloat16_as_ushort(h2) | ((uint32_t)__bfloat16_as_ushort(h3) << 16);
    L.x = (uint32_t)__bfloat16_as_ushort(l0) | ((uint32_t)__bfloat16_as_ushort(l1) << 16);
    L.y = (uint32_t)__bfloat16_as_ushort(l2) | ((uint32_t)__bfloat16_as_ushort(l3) << 16);
    hi[i] = H; lo[i] = L;
}

// fp32 -> fp16 hi/lo split
__global__ void splitH_kernel(const float4* __restrict__ in,
                              uint2* __restrict__ hi, uint2* __restrict__ lo, int n4)
{
    int i = blockIdx.x * blockDim.x + threadIdx.x;
    if (i >= n4) return;
    float4 v = in[i];
    __half h0 = __float2half_rn(v.x), h1 = __float2half_rn(v.y);
    __half h2 = __float2half_rn(v.z), h3 = __float2half_rn(v.w);
    __half l0 = __float2half_rn(v.x - __half2float(h0));
    __half l1 = __float2half_rn(v.y - __half2float(h1));
    __half l2 = __float2half_rn(v.z - __half2float(h2));
    __half l3 = __float2half_rn(v.w - __half2float(h3));
    uint2 H, L;
    H.x = (uint32_t)__half_as_ushort(h0) | ((uint32_t)__half_as_ushort(h1) << 16);
    H.y = (uint32_t)__half_as_ushort(h2) | ((uint32_t)__half_as_ushort(h3) << 16);
    L.x = (uint32_t)__half_as_ushort(l0) | ((uint32_t)__half_as_ushort(l1) << 16);
    L.y = (uint32_t)__half_as_ushort(l2) | ((uint32_t)__half_as_ushort(l3) << 16);
    hi[i] = H; lo[i] = L;
}

// fp32 -> fp16 convert (no residual)
__global__ void convH_kernel(const float4* __restrict__ in, uint2* __restrict__ out, int n4)
{
    int i = blockIdx.x * blockDim.x + threadIdx.x;
    if (i >= n4) return;
    float4 v = in[i];
    uint2 O;
    O.x = (uint32_t)__half_as_ushort(__float2half_rn(v.x))
        | ((uint32_t)__half_as_ushort(__float2half_rn(v.y)) << 16);
    O.y = (uint32_t)__half_as_ushort(__float2half_rn(v.z))
        | ((uint32_t)__half_as_ushort(__float2half_rn(v.w)) << 16);
    out[i] = O;
}

// broadcast final state (fp16 hi+lo -> fp32, all timesteps)
__global__ void bcastH_kernel(const uint2* __restrict__ hi, const uint2* __restrict__ lo,
                              float4* __restrict__ out)
{
    int i = blockIdx.x * blockDim.x + threadIdx.x;
    int b  = i >> 16;
    int s4 = i & 255;
    uint2 H = hi[(b << 8) + s4];
    uint2 L = lo[(b << 8) + s4];
    float4 o;
    o.x = __half2float(__ushort_as_half((unsigned short)(H.x & 0xFFFF)))
        + __half2float(__ushort_as_half((unsigned short)(L.x & 0xFFFF)));
    o.y = __half2float(__ushort_as_half((unsigned short)(H.x >> 16)))
        + __half2float(__ushort_as_half((unsigned short)(L.x >> 16)));
    o.z = __half2float(__ushort_as_half((unsigned short)(H.y & 0xFFFF)))
        + __half2float(__ushort_as_half((unsigned short)(L.y & 0xFFFF)));
    o.w = __half2float(__ushort_as_half((unsigned short)(H.y >> 16)))
        + __half2float(__ushort_as_half((unsigned short)(L.y >> 16)));
    out[i] = o;
}

// ---------------- driver ----------------------------------------------------
extern "C" void kernel_launch(void* const* d_in, const int* in_sizes, int n_in,
                              void* d_out, int out_size)
{
    const float* x      = (const float*)d_in[0];
    const float* W_in   = (const float*)d_in[1];
    const float* b_in   = (const float*)d_in[2];
    const float* W_rec  = (const float*)d_in[3];
    const float* b_rec  = (const float*)d_in[4];
    const float* W_rec2 = (const float*)d_in[5];
    const float* b_rec2 = (const float*)d_in[6];
    float* out = (float*)d_out;

    float* ext;
    __half *sAh, *sAl, *sBh, *sBl, *W1, *W2;
    __nv_bfloat16 *xh, *xl, *Winh, *Winl;
    cudaGetSymbolAddress((void**)&ext, g_ext);
    cudaGetSymbolAddress((void**)&sAh, g_sAh);
    cudaGetSymbolAddress((void**)&sAl, g_sAl);
    cudaGetSymbolAddress((void**)&sBh, g_sBh);
    cudaGetSymbolAddress((void**)&sBl, g_sBl);
    cudaGetSymbolAddress((void**)&W1,  g_W1);
    cudaGetSymbolAddress((void**)&W2,  g_W2);
    cudaGetSymbolAddress((void**)&xh,  g_xh);
    cudaGetSymbolAddress((void**)&xl,  g_xl);
    cudaGetSymbolAddress((void**)&Winh, g_Winh);
    cudaGetSymbolAddress((void**)&Winl, g_Winl);

    cudaFuncSetAttribute(proj_mma, cudaFuncAttributeMaxDynamicSharedMemorySize, P_SM);

    // barrier counter reset (every call — graph replays reuse it)
    zero_ctr<<<1, 1>>>();

    // weights -> fp16
    convH_kernel<<<(SS * SS / 4) / 256, 256>>>((const float4*)W_rec,  (uint2*)W1, SS * SS / 4);
    convH_kernel<<<(SS * SS / 4) / 256, 256>>>((const float4*)W_rec2, (uint2*)W2, SS * SS / 4);

    // x, W_in -> bf16 hi/lo for projection
    splitBF_kernel<<<((size_t)BB * TT * IND / 4 + 255) / 256, 256>>>(
        (const float4*)x, (uint2*)xh, (uint2*)xl, BB * TT * IND / 4);
    splitBF_kernel<<<(SS * IND / 4 + 255) / 256, 256>>>(
        (const float4*)W_in, (uint2*)Winh, (uint2*)Winl, SS * IND / 4);

    // Phase 1: ext = x @ W_in^T + b_in
    {
        dim3 grid((BB * TT) / 64, SS / 64);
        proj_mma<<<grid, 256, P_SM>>>(xh, xl, Winh, Winl, b_in, ext);
    }

    // Initial state: s0 = 0 + ext[0] -> fp16 hi/lo
    splitH_kernel<<<(BB * SS / 4) / 256, 256>>>((const float4*)ext, (uint2*)sAh, (uint2*)sAl, BB * SS / 4);

    // Phase 2: whole scan in ONE persistent kernel (128 CTAs, co-resident)
    {
        dim3 grid(BB / M_TILE, SS / N_TILE);   // (8, 16) = 128 CTAs
        scan_kernel<<<grid, 256>>>(sAh, sAl, sBh, sBl, W1, W2, b_rec, b_rec2, ext);
    }

    // Phase 3: broadcast final state
    bcastH_kernel<<<(BB * TT * SS / 4) / 256, 256>>>((const uint2*)sAh, (const uint2*)sAl, (float4*)out);
}

// round 6
// speedup vs baseline: 1.6406x; 1.6406x over previous
#include <cuda_runtime.h>
#include <cuda_bf16.h>
#include <cuda_fp16.h>
#include <cstdint>

// Problem dims
#define BB  256
#define TT  256
#define IND 128
#define SS  1024

// ---------------- scratch (__device__ globals) ------------------------------
__device__ float g_ext[(size_t)TT * BB * SS];            // [t][b][s] fp32
__device__ __half g_sAh[BB * SS], g_sAl[BB * SS];        // state hi/lo fp16
__device__ __half g_sBh[BB * SS], g_sBl[BB * SS];
__device__ __half g_W1[SS * SS], g_W2[SS * SS];          // weights plain fp16
__device__ __nv_bfloat16 g_xh[(size_t)BB * TT * IND], g_xl[(size_t)BB * TT * IND];
__device__ __nv_bfloat16 g_Winh[SS * IND], g_Winl[SS * IND];

// ---------------- helpers ---------------------------------------------------
__device__ __forceinline__ uint32_t smem_u32(const void* p) {
    uint32_t a;
    asm("{ .reg .u64 t; cvta.to.shared.u64 t, %1; cvt.u32.u64 %0, t; }" : "=r"(a) : "l"(p));
    return a;
}
__device__ __forceinline__ void cp16(uint32_t dst, const void* src) {
    asm volatile("cp.async.cg.shared.global [%0], [%1], 16;" :: "r"(dst), "l"(src));
}
__device__ __forceinline__ void cp_commit() { asm volatile("cp.async.commit_group;"); }
__device__ __forceinline__ void cp_wait0()  { asm volatile("cp.async.wait_group 0;"); }
__device__ __forceinline__ void cp_wait1()  { asm volatile("cp.async.wait_group 1;"); }

__device__ __forceinline__ void mma_bf16(float* c, const uint32_t* a,
                                         uint32_t b0, uint32_t b1) {
    asm volatile(
        "mma.sync.aligned.m16n8k16.row.col.f32.bf16.bf16.f32 "
        "{%0,%1,%2,%3}, {%4,%5,%6,%7}, {%8,%9}, {%0,%1,%2,%3};"
        : "+f"(c[0]), "+f"(c[1]), "+f"(c[2]), "+f"(c[3])
        : "r"(a[0]), "r"(a[1]), "r"(a[2]), "r"(a[3]), "r"(b0), "r"(b1));
}
__device__ __forceinline__ void mma_f16(float* c, const uint32_t* a,
                                        uint32_t b0, uint32_t b1) {
    asm volatile(
        "mma.sync.aligned.m16n8k16.row.col.f32.f16.f16.f32 "
        "{%0,%1,%2,%3}, {%4,%5,%6,%7}, {%8,%9}, {%0,%1,%2,%3};"
        : "+f"(c[0]), "+f"(c[1]), "+f"(c[2]), "+f"(c[3])
        : "r"(a[0]), "r"(a[1]), "r"(a[2]), "r"(a[3]), "r"(b0), "r"(b1));
}
__device__ __forceinline__ void ldsm_x4(uint32_t* r, uint32_t addr) {
    asm volatile("ldmatrix.sync.aligned.m8n8.x4.shared.b16 {%0,%1,%2,%3}, [%4];"
                 : "=r"(r[0]), "=r"(r[1]), "=r"(r[2]), "=r"(r[3]) : "r"(addr));
}

// ---------------- layer GEMM (fp16 2-term, one launch per layer) ------------
// O = relu((Ah+Al) @ W^T + bias) (+ ext_next). CTA tile 32x64, KC=64,
// 2-stage cp.async, 256 threads, warp tile 16x16, ldmatrix, XOR swizzle.
#define M_TILE 32
#define N_TILE 64
#define KC     64
#define NCHUNK (SS / KC)          // 16
#define A_HI 0
#define A_LO 4096
#define B_W  8192
#define STAGE_BYTES 16384
#define SM_TOTAL (2 * STAGE_BYTES)   // 32768

__device__ __forceinline__ void load_chunk_h(
    uint32_t st, int kc0, int tid, int m0, int n0,
    const __half* __restrict__ Ah, const __half* __restrict__ Al,
    const __half* __restrict__ W)
{
    #pragma unroll
    for (int i = 0; i < 4; i++) {
        int u = tid + (i << 8);              // 0..1023
        const __half* src;
        uint32_t dst;
        if (u < 512) {                       // A hi (0..255), A lo (256..511)
            int sel = u >> 8, v = u & 255;
            int row = v >> 3, cu = v & 7;
            src = (sel ? Al : Ah) + (size_t)(m0 + row) * SS + kc0 + cu * 8;
            dst = st + (sel ? A_LO : A_HI) + row * 128 + ((cu ^ (row & 7)) << 4);
        } else {                             // B (512..1023)
            int v = u - 512;
            int row = v >> 3, cu = v & 7;
            src = W + (size_t)(n0 + row) * SS + kc0 + cu * 8;
            dst = st + B_W + row * 128 + ((cu ^ (row & 7)) << 4);
        }
        cp16(dst, src);
    }
    cp_commit();
}

__global__ __launch_bounds__(256) void layer_kernel(
    const __half* __restrict__ Ah, const __half* __restrict__ Al,
    const __half* __restrict__ W,
    const float* __restrict__ bias, const float* __restrict__ ext_next,
    __half* __restrict__ Oh, __half* __restrict__ Ol)
{
    extern __shared__ char smem[];
    const uint32_t sb = smem_u32(smem);
    const int tid = threadIdx.x;
    const int wid = tid >> 5, lane = tid & 31;
    const int g = lane >> 2, t4 = lane & 3;
    const int wm = (wid >> 2) << 4;          // 0/16
    const int wn = (wid & 3) << 4;           // 0/16/32/48
    const int m0 = blockIdx.x * M_TILE, n0 = blockIdx.y * N_TILE;

    const int lr = lane & 7;
    const int half8 = (lane >> 3) & 1;
    const int khalf = (lane >> 4) & 1;
    const int rowA = wm + half8 * 8 + lr;
    const int rowB = wn + half8 * 8 + lr;
    const int swA = rowA & 7, swB = rowB & 7;
    const uint32_t aH0 = sb + A_HI + rowA * 128;
    const uint32_t aL0 = sb + A_LO + rowA * 128;
    const uint32_t bW0 = sb + B_W  + rowB * 128;

    float acc[2][4] = {};

    load_chunk_h(sb, 0, tid, m0, n0, Ah, Al, W);

    #pragma unroll 1
    for (int c = 0; c < NCHUNK; c++) {
        if (c + 1 < NCHUNK) {
            load_chunk_h(sb + ((c + 1) & 1) * STAGE_BYTES, (c + 1) * KC,
                         tid, m0, n0, Ah, Al, W);
            cp_wait1();
        } else {
            cp_wait0();
        }
        __syncthreads();

        const uint32_t stg = (c & 1) * STAGE_BYTES;
        #pragma unroll
        for (int ks = 0; ks < 4; ks++) {
            const int u = ks * 2 + khalf;
            uint32_t ah[4], al[4], bw[4];
            ldsm_x4(ah, aH0 + stg + ((u ^ swA) << 4));
            ldsm_x4(al, aL0 + stg + ((u ^ swA) << 4));
            ldsm_x4(bw, bW0 + stg + ((u ^ swB) << 4));
            mma_f16(acc[0], ah, bw[0], bw[2]);
            mma_f16(acc[0], al, bw[0], bw[2]);
            mma_f16(acc[1], ah, bw[1], bw[3]);
            mma_f16(acc[1], al, bw[1], bw[3]);
        }
        __syncthreads();
    }

    // Epilogue: bias + relu (+ ext_next) + fp16 hi/lo split + store
    const int row0 = m0 + wm + g;
    const int row1 = row0 + 8;
    #pragma unroll
    for (int j = 0; j < 2; j++) {
        const int col = n0 + wn + j * 8 + t4 * 2;
        float2 bb = *(const float2*)(bias + col);
        float v00 = fmaxf(acc[j][0] + bb.x, 0.0f);
        float v01 = fmaxf(acc[j][1] + bb.y, 0.0f);
        float v10 = fmaxf(acc[j][2] + bb.x, 0.0f);
        float v11 = fmaxf(acc[j][3] + bb.y, 0.0f);
        if (ext_next) {
            float2 e0 = *(const float2*)(ext_next + (size_t)row0 * SS + col);
            float2 e1 = *(const float2*)(ext_next + (size_t)row1 * SS + col);
            v00 += e0.x; v01 += e0.y; v10 += e1.x; v11 += e1.y;
        }
        __half h00 = __float2half_rn(v00), h01 = __float2half_rn(v01);
        __half h10 = __float2half_rn(v10), h11 = __float2half_rn(v11);
        __half l00 = __float2half_rn(v00 - __half2float(h00));
        __half l01 = __float2half_rn(v01 - __half2float(h01));
        __half l10 = __float2half_rn(v10 - __half2float(h10));
        __half l11 = __float2half_rn(v11 - __half2float(h11));
        *(uint32_t*)(Oh + (size_t)row0 * SS + col) =
            (uint32_t)__half_as_ushort(h00) | ((uint32_t)__half_as_ushort(h01) << 16);
        *(uint32_t*)(Oh + (size_t)row1 * SS + col) =
            (uint32_t)__half_as_ushort(h10) | ((uint32_t)__half_as_ushort(h11) << 16);
        *(uint32_t*)(Ol + (size_t)row0 * SS + col) =
            (uint32_t)__half_as_ushort(l00) | ((uint32_t)__half_as_ushort(l01) << 16);
        *(uint32_t*)(Ol + (size_t)row1 * SS + col) =
            (uint32_t)__half_as_ushort(l10) | ((uint32_t)__half_as_ushort(l11) << 16);
    }
}

// ---------------- input projection (bf16 3-term MMA) ------------------------
#define PA_HI 0
#define PA_LO 16384
#define PB_HI 32768
#define PB_LO 49152
#define P_SM  65536

__global__ __launch_bounds__(256) void proj_mma(
    const __nv_bfloat16* __restrict__ Xh, const __nv_bfloat16* __restrict__ Xl,
    const __nv_bfloat16* __restrict__ Wh, const __nv_bfloat16* __restrict__ Wl,
    const float* __restrict__ bias, float* __restrict__ Out)
{
    extern __shared__ char smem[];
    const uint32_t sb = smem_u32(smem);
    const int tid = threadIdx.x;
    const int wid = tid >> 5, lane = tid & 31;
    const int g = lane >> 2, t4 = lane & 3;
    const int wm = (wid >> 1) << 4;          // 0..48
    const int wn = (wid & 1) << 5;           // 0/32
    const int m0 = blockIdx.x * 64, n0 = blockIdx.y * 64;

    #pragma unroll
    for (int i = 0; i < 16; i++) {
        int u = tid + (i << 8);              // 0..4095
        const __nv_bfloat16* src;
        uint32_t dst;
        if (u < 2048) {
            int sel = u >> 10, v = u & 1023;
            int row = v >> 4, cu = v & 15;
            src = (sel ? Xl : Xh) + (size_t)(m0 + row) * IND + cu * 8;
            dst = sb + (sel ? PA_LO : PA_HI) + row * 256
                + (((cu & 8) | ((cu & 7) ^ (row & 7))) << 4);
        } else {
            int w = u - 2048;
            int sel = w >> 10, v = w & 1023;
            int row = v >> 4, cu = v & 15;
            src = (sel ? Wl : Wh) + (size_t)(n0 + row) * IND + cu * 8;
            dst = sb + (sel ? PB_LO : PB_HI) + row * 256
                + (((cu & 8) | ((cu & 7) ^ (row & 7))) << 4);
        }
        cp16(dst, src);
    }
    cp_commit();
    cp_wait0();
    __syncthreads();

    const int lr = lane & 7;
    const int half8 = (lane >> 3) & 1;
    const int khalf = (lane >> 4) & 1;
    const int rowA = wm + half8 * 8 + lr;
    const int rowB = wn + half8 * 8 + lr;
    const int swA = rowA & 7, swB = rowB & 7;

    float acc[4][4] = {};
    #pragma unroll
    for (int ks = 0; ks < 8; ks++) {
        const int u = ks * 2 + khalf;
        const uint32_t puA = (((u & 8) | ((u & 7) ^ swA)) << 4);
        const uint32_t puB = (((u & 8) | ((u & 7) ^ swB)) << 4);
        uint32_t ah[4], al[4];
        ldsm_x4(ah, sb + PA_HI + rowA * 256 + puA);
        ldsm_x4(al, sb + PA_LO + rowA * 256 + puA);
        #pragma unroll
        for (int jj = 0; jj < 2; jj++) {
            uint32_t bh[4], bl[4];
            ldsm_x4(bh, sb + PB_HI + (rowB + jj * 16) * 256 + puB);
            ldsm_x4(bl, sb + PB_LO + (rowB + jj * 16) * 256 + puB);
            mma_bf16(acc[jj * 2],     ah, bh[0], bh[2]);
            mma_bf16(acc[jj * 2],     ah, bl[0], bl[2]);
            mma_bf16(acc[jj * 2],     al, bh[0], bh[2]);
            mma_bf16(acc[jj * 2 + 1], ah, bh[1], bh[3]);
            mma_bf16(acc[jj * 2 + 1], ah, bl[1], bl[3]);
            mma_bf16(acc[jj * 2 + 1], al, bh[1], bh[3]);
        }
    }

    const int r0 = m0 + wm + g;
    const int r1 = r0 + 8;
    const int b0r = r0 >> 8, t0r = r0 & 255;
    const int b1r = r1 >> 8, t1r = r1 & 255;
    #pragma unroll
    for (int j = 0; j < 4; j++) {
        const int col = n0 + wn + j * 8 + t4 * 2;
        float2 bb = *(const float2*)(bias + col);
        float2 o0 = make_float2(acc[j][0] + bb.x, acc[j][1] + bb.y);
        float2 o1 = make_float2(acc[j][2] + bb.x, acc[j][3] + bb.y);
        *(float2*)(Out + ((size_t)t0r * BB + b0r) * SS + col) = o0;
        *(float2*)(Out + ((size_t)t1r * BB + b1r) * SS + col) = o1;
    }
}

// ---------------- conversion kernels ----------------------------------------
__global__ void splitBF_kernel(const float4* __restrict__ in,
                               uint2* __restrict__ hi, uint2* __restrict__ lo, int n4)
{
    int i = blockIdx.x * blockDim.x + threadIdx.x;
    if (i >= n4) return;
    float4 v = in[i];
    __nv_bfloat16 h0 = __float2bfloat16(v.x), h1 = __float2bfloat16(v.y);
    __nv_bfloat16 h2 = __float2bfloat16(v.z), h3 = __float2bfloat16(v.w);
    __nv_bfloat16 l0 = __float2bfloat16(v.x - __bfloat162float(h0));
    __nv_bfloat16 l1 = __float2bfloat16(v.y - __bfloat162float(h1));
    __nv_bfloat16 l2 = __float2bfloat16(v.z - __bfloat162float(h2));
    __nv_bfloat16 l3 = __float2bfloat16(v.w - __bfloat162float(h3));
    uint2 H, L;
    H.x = (uint32_t)__bfloat16_as_ushort(h0) | ((uint32_t)__bfloat16_as_ushort(h1) << 16);
    H.y = (uint32_t)__bfloat16_as_ushort(h2) | ((uint32_t)__bfloat16_as_ushort(h3) << 16);
    L.x = (uint32_t)__bfloat16_as_ushort(l0) | ((uint32_t)__bfloat16_as_ushort(l1) << 16);
    L.y = (uint32_t)__bfloat16_as_ushort(l2) | ((uint32_t)__bfloat16_as_ushort(l3) << 16);
    hi[i] = H; lo[i] = L;
}

__global__ void splitH_kernel(const float4* __restrict__ in,
                              uint2* __restrict__ hi, uint2* __restrict__ lo, int n4)
{
    int i = blockIdx.x * blockDim.x + threadIdx.x;
    if (i >= n4) return;
    float4 v = in[i];
    __half h0 = __float2half_rn(v.x), h1 = __float2half_rn(v.y);
    __half h2 = __float2half_rn(v.z), h3 = __float2half_rn(v.w);
    __half l0 = __float2half_rn(v.x - __half2float(h0));
    __half l1 = __float2half_rn(v.y - __half2float(h1));
    __half l2 = __float2half_rn(v.z - __half2float(h2));
    __half l3 = __float2half_rn(v.w - __half2float(h3));
    uint2 H, L;
    H.x = (uint32_t)__half_as_ushort(h0) | ((uint32_t)__half_as_ushort(h1) << 16);
    H.y = (uint32_t)__half_as_ushort(h2) | ((uint32_t)__half_as_ushort(h3) << 16);
    L.x = (uint32_t)__half_as_ushort(l0) | ((uint32_t)__half_as_ushort(l1) << 16);
    L.y = (uint32_t)__half_as_ushort(l2) | ((uint32_t)__half_as_ushort(l3) << 16);
    hi[i] = H; lo[i] = L;
}

__global__ void convH_kernel(const float4* __restrict__ in, uint2* __restrict__ out, int n4)
{
    int i = blockIdx.x * blockDim.x + threadIdx.x;
    if (i >= n4) return;
    float4 v = in[i];
    uint2 O;
    O.x = (uint32_t)__half_as_ushort(__float2half_rn(v.x))
        | ((uint32_t)__half_as_ushort(__float2half_rn(v.y)) << 16);
    O.y = (uint32_t)__half_as_ushort(__float2half_rn(v.z))
        | ((uint32_t)__half_as_ushort(__float2half_rn(v.w)) << 16);
    out[i] = O;
}

__global__ void bcastH_kernel(const uint2* __restrict__ hi, const uint2* __restrict__ lo,
                              float4* __restrict__ out)
{
    int i = blockIdx.x * blockDim.x + threadIdx.x;
    int b  = i >> 16;
    int s4 = i & 255;
    uint2 H = hi[(b << 8) + s4];
    uint2 L = lo[(b << 8) + s4];
    float4 o;
    o.x = __half2float(__ushort_as_half((unsigned short)(H.x & 0xFFFF)))
        + __half2float(__ushort_as_half((unsigned short)(L.x & 0xFFFF)));
    o.y = __half2float(__ushort_as_half((unsigned short)(H.x >> 16)))
        + __half2float(__ushort_as_half((unsigned short)(L.x >> 16)));
    o.z = __half2float(__ushort_as_half((unsigned short)(H.y & 0xFFFF)))
        + __half2float(__ushort_as_half((unsigned short)(L.y & 0xFFFF)));
    o.w = __half2float(__ushort_as_half((unsigned short)(H.y >> 16)))
        + __half2float(__ushort_as_half((unsigned short)(L.y >> 16)));
    out[i] = o;
}

// ---------------- driver ----------------------------------------------------
extern "C" void kernel_launch(void* const* d_in, const int* in_sizes, int n_in,
                              void* d_out, int out_size)
{
    const float* x      = (const float*)d_in[0];
    const float* W_in   = (const float*)d_in[1];
    const float* b_in   = (const float*)d_in[2];
    const float* W_rec  = (const float*)d_in[3];
    const float* b_rec  = (const float*)d_in[4];
    const float* W_rec2 = (const float*)d_in[5];
    const float* b_rec2 = (const float*)d_in[6];
    float* out = (float*)d_out;

    float* ext;
    __half *sAh, *sAl, *sBh, *sBl, *W1, *W2;
    __nv_bfloat16 *xh, *xl, *Winh, *Winl;
    cudaGetSymbolAddress((void**)&ext, g_ext);
    cudaGetSymbolAddress((void**)&sAh, g_sAh);
    cudaGetSymbolAddress((void**)&sAl, g_sAl);
    cudaGetSymbolAddress((void**)&sBh, g_sBh);
    cudaGetSymbolAddress((void**)&sBl, g_sBl);
    cudaGetSymbolAddress((void**)&W1,  g_W1);
    cudaGetSymbolAddress((void**)&W2,  g_W2);
    cudaGetSymbolAddress((void**)&xh,  g_xh);
    cudaGetSymbolAddress((void**)&xl,  g_xl);
    cudaGetSymbolAddress((void**)&Winh, g_Winh);
    cudaGetSymbolAddress((void**)&Winl, g_Winl);

    cudaFuncSetAttribute(layer_kernel, cudaFuncAttributeMaxDynamicSharedMemorySize, SM_TOTAL);
    cudaFuncSetAttribute(proj_mma,     cudaFuncAttributeMaxDynamicSharedMemorySize, P_SM);

    // weights -> fp16
    convH_kernel<<<(SS * SS / 4) / 256, 256>>>((const float4*)W_rec,  (uint2*)W1, SS * SS / 4);
    convH_kernel<<<(SS * SS / 4) / 256, 256>>>((const float4*)W_rec2, (uint2*)W2, SS * SS / 4);

    // x, W_in -> bf16 hi/lo for projection
    splitBF_kernel<<<((size_t)BB * TT * IND / 4 + 255) / 256, 256>>>(
        (const float4*)x, (uint2*)xh, (uint2*)xl, BB * TT * IND / 4);
    splitBF_kernel<<<(SS * IND / 4 + 255) / 256, 256>>>(
        (const float4*)W_in, (uint2*)Winh, (uint2*)Winl, SS * IND / 4);

    // Phase 1: ext = x @ W_in^T + b_in
    {
        dim3 grid((BB * TT) / 64, SS / 64);
        proj_mma<<<grid, 256, P_SM>>>(xh, xl, Winh, Winl, b_in, ext);
    }

    // Initial state: s0 = 0 + ext[0] -> fp16 hi/lo
    splitH_kernel<<<(BB * SS / 4) / 256, 256>>>((const float4*)ext, (uint2*)sAh, (uint2*)sAl, BB * SS / 4);

    // Phase 2: 256 steps x 2 layers, one launch per layer
    {
        dim3 grid(BB / M_TILE, SS / N_TILE);   // (8, 16) = 128 CTAs
        for (int t = 0; t < TT; t++) {
            layer_kernel<<<grid, 256, SM_TOTAL>>>(sAh, sAl, W1, b_rec, nullptr, sBh, sBl);
            const float* en = (t + 1 < TT) ? ext + (size_t)(t + 1) * BB * SS : nullptr;
            layer_kernel<<<grid, 256, SM_TOTAL>>>(sBh, sBl, W2, b_rec2, en, sAh, sAl);
        }
    }

    // Phase 3: broadcast final state
    bcastH_kernel<<<(BB * TT * SS / 4) / 256, 256>>>((const uint2*)sAh, (const uint2*)sAl, (float4*)out);
}

// round 7
// speedup vs baseline: 1.7451x; 1.0637x over previous
#include <cuda_runtime.h>
#include <cuda_bf16.h>
#include <cuda_fp16.h>
#include <cstdint>

// Problem dims
#define BB  256
#define TT  256
#define IND 128
#define SS  1024

// ---------------- scratch (__device__ globals) ------------------------------
__device__ float g_ext[(size_t)TT * BB * SS];            // [t][b][s] fp32
__device__ __half g_sAh[BB * SS], g_sAl[BB * SS];        // state hi/lo fp16
__device__ __half g_sBh[BB * SS], g_sBl[BB * SS];
__device__ __half g_W1[SS * SS], g_W2[SS * SS];          // weights plain fp16
__device__ __nv_bfloat16 g_xh[(size_t)BB * TT * IND], g_xl[(size_t)BB * TT * IND];
__device__ __nv_bfloat16 g_Winh[SS * IND], g_Winl[SS * IND];

// ---------------- helpers ---------------------------------------------------
__device__ __forceinline__ uint32_t smem_u32(const void* p) {
    uint32_t a;
    asm("{ .reg .u64 t; cvta.to.shared.u64 t, %1; cvt.u32.u64 %0, t; }" : "=r"(a) : "l"(p));
    return a;
}
__device__ __forceinline__ void cp16(uint32_t dst, const void* src) {
    asm volatile("cp.async.cg.shared.global [%0], [%1], 16;" :: "r"(dst), "l"(src));
}
__device__ __forceinline__ void cp_commit() { asm volatile("cp.async.commit_group;"); }
__device__ __forceinline__ void cp_wait0()  { asm volatile("cp.async.wait_group 0;"); }
__device__ __forceinline__ void cp_wait1()  { asm volatile("cp.async.wait_group 1;"); }
__device__ __forceinline__ void gdc_wait()   { asm volatile("griddepcontrol.wait;" ::: "memory"); }
__device__ __forceinline__ void gdc_launch() { asm volatile("griddepcontrol.launch_dependents;"); }

__device__ __forceinline__ void mma_bf16(float* c, const uint32_t* a,
                                         uint32_t b0, uint32_t b1) {
    asm volatile(
        "mma.sync.aligned.m16n8k16.row.col.f32.bf16.bf16.f32 "
        "{%0,%1,%2,%3}, {%4,%5,%6,%7}, {%8,%9}, {%0,%1,%2,%3};"
        : "+f"(c[0]), "+f"(c[1]), "+f"(c[2]), "+f"(c[3])
        : "r"(a[0]), "r"(a[1]), "r"(a[2]), "r"(a[3]), "r"(b0), "r"(b1));
}
__device__ __forceinline__ void mma_f16(float* c, const uint32_t* a,
                                        uint32_t b0, uint32_t b1) {
    asm volatile(
        "mma.sync.aligned.m16n8k16.row.col.f32.f16.f16.f32 "
        "{%0,%1,%2,%3}, {%4,%5,%6,%7}, {%8,%9}, {%0,%1,%2,%3};"
        : "+f"(c[0]), "+f"(c[1]), "+f"(c[2]), "+f"(c[3])
        : "r"(a[0]), "r"(a[1]), "r"(a[2]), "r"(a[3]), "r"(b0), "r"(b1));
}
__device__ __forceinline__ void ldsm_x4(uint32_t* r, uint32_t addr) {
    asm volatile("ldmatrix.sync.aligned.m8n8.x4.shared.b16 {%0,%1,%2,%3}, [%4];"
                 : "=r"(r[0]), "=r"(r[1]), "=r"(r[2]), "=r"(r[3]) : "r"(addr));
}

// ---------------- layer GEMM (fp16 2-term, warp K-split, PDL) ---------------
// O = relu((Ah+Al) @ W^T + bias) (+ ext_next). CTA tile 32x64, KC=64.
// 8 warps: (wm2 x wn2 x kslot2), warp tile 16x32, each warp does half the
// K-steps of its tile; pair reduction via SMEM at the end.
// A: 2-stage (8KB each: hi+lo), B: 3-stage (8KB each). B chunks c, c+1 are
// prefetched BEFORE griddepcontrol.wait (weights don't depend on prev layer).
#define M_TILE 32
#define N_TILE 64
#define KC     64
#define NCHUNK (SS / KC)          // 16
#define ASTG   8192               // A stage: hi 4KB + lo 4KB
#define A_LO_OFF 4096
#define B_OFF  16384
#define BSTG   8192
#define SM_TOTAL (B_OFF + 3 * BSTG)   // 40960

__device__ __forceinline__ void load_A(uint32_t st, int kc0, int tid, int m0,
    const __half* __restrict__ Ah, const __half* __restrict__ Al)
{
    #pragma unroll
    for (int i = 0; i < 2; i++) {
        int u = tid + (i << 8);          // 0..511
        int sel = u >> 8;                // 0 hi, 1 lo
        int v = u & 255;
        int row = v >> 3, cu = v & 7;
        const __half* src = (sel ? Al : Ah) + (size_t)(m0 + row) * SS + kc0 + cu * 8;
        cp16(st + (sel ? A_LO_OFF : 0) + row * 128 + ((cu ^ (row & 7)) << 4), src);
    }
}
__device__ __forceinline__ void load_B(uint32_t st, int kc0, int tid, int n0,
    const __half* __restrict__ W)
{
    #pragma unroll
    for (int i = 0; i < 2; i++) {
        int u = tid + (i << 8);          // 0..511
        int row = u >> 3, cu = u & 7;    // 64 rows x 8 units
        const __half* src = W + (size_t)(n0 + row) * SS + kc0 + cu * 8;
        cp16(st + row * 128 + ((cu ^ (row & 7)) << 4), src);
    }
}

__global__ __launch_bounds__(256) void layer_kernel(
    const __half* __restrict__ Ah, const __half* __restrict__ Al,
    const __half* __restrict__ W,
    const float* __restrict__ bias, const float* __restrict__ ext_next,
    __half* __restrict__ Oh, __half* __restrict__ Ol)
{
    extern __shared__ char smem[];
    const uint32_t sb = smem_u32(smem);
    const int tid = threadIdx.x;
    const int wid = tid >> 5, lane = tid & 31;
    const int g = lane >> 2, t4 = lane & 3;
    const int wm = (wid >> 2) & 1;       // 0/1  -> rows wm*16
    const int wn = (wid >> 1) & 1;       // 0/1  -> cols wn*32
    const int kslot = wid & 1;           // K half
    const int m0 = blockIdx.x * M_TILE, n0 = blockIdx.y * N_TILE;

    const int lr = lane & 7;
    const int half8 = (lane >> 3) & 1;
    const int khalf = (lane >> 4) & 1;
    const int rowA  = wm * 16 + half8 * 8 + lr;
    const int rowB0 = wn * 32 + half8 * 8 + lr;
    const int rowB1 = rowB0 + 16;
    const int swA = rowA & 7, swB0 = rowB0 & 7, swB1 = rowB1 & 7;

    // Prefetch weight chunks 0,1 BEFORE the grid dependency (W is static).
    load_B(sb + B_OFF, 0, tid, n0, W);           cp_commit();   // g0
    load_B(sb + B_OFF + BSTG, KC, tid, n0, W);   cp_commit();   // g1
    gdc_wait();                                   // prev layer fully done
    load_A(sb, 0, tid, m0, Ah, Al);              cp_commit();   // g2

    float acc[4][4] = {};
    int bs = 0, bnext = 2;

    #pragma unroll 1
    for (int c = 0; c < NCHUNK; c++) {
        if (c <= NCHUNK - 3) {
            load_A(sb + ((c + 1) & 1) * ASTG, (c + 1) * KC, tid, m0, Ah, Al);
            load_B(sb + B_OFF + bnext * BSTG, (c + 2) * KC, tid, n0, W);
            cp_commit();
        } else if (c == NCHUNK - 2) {
            load_A(sb + ((c + 1) & 1) * ASTG, (c + 1) * KC, tid, m0, Ah, Al);
            cp_commit();
        }
        if (c < NCHUNK - 1) cp_wait1(); else cp_wait0();
        __syncthreads();

        const uint32_t aBase = sb + (c & 1) * ASTG;
        const uint32_t bBase = sb + B_OFF + bs * BSTG;
        #pragma unroll
        for (int k2 = 0; k2 < 2; k2++) {
            const int u = (kslot * 2 + k2) * 2 + khalf;
            uint32_t ah[4], al[4], b0[4], b1[4];
            ldsm_x4(ah, aBase + rowA * 128 + ((u ^ swA) << 4));
            ldsm_x4(al, aBase + A_LO_OFF + rowA * 128 + ((u ^ swA) << 4));
            ldsm_x4(b0, bBase + rowB0 * 128 + ((u ^ swB0) << 4));
            ldsm_x4(b1, bBase + rowB1 * 128 + ((u ^ swB1) << 4));
            mma_f16(acc[0], ah, b0[0], b0[2]);
            mma_f16(acc[1], ah, b0[1], b0[3]);
            mma_f16(acc[2], ah, b1[0], b1[2]);
            mma_f16(acc[3], ah, b1[1], b1[3]);
            mma_f16(acc[0], al, b0[0], b0[2]);
            mma_f16(acc[1], al, b0[1], b0[3]);
            mma_f16(acc[2], al, b1[0], b1[2]);
            mma_f16(acc[3], al, b1[1], b1[3]);
        }
        __syncthreads();
        bs    = (bs    == 2) ? 0 : bs + 1;
        bnext = (bnext == 2) ? 0 : bnext + 1;
    }

    // Cross-warp K reduction: kslot=1 warps dump accs, kslot=0 warps combine.
    float* scr = (float*)smem;               // 8KB scratch (stages done)
    const int pair = wid >> 1;               // 0..3 = (wm,wn)
    if (kslot == 1) {
        float4* p = (float4*)(scr + pair * 512 + lane * 16);
        #pragma unroll
        for (int jj = 0; jj < 4; jj++)
            p[jj] = make_float4(acc[jj][0], acc[jj][1], acc[jj][2], acc[jj][3]);
    }
    __syncthreads();
    if (kslot == 0) {
        const float4* p = (const float4*)(scr + pair * 512 + lane * 16);
        #pragma unroll
        for (int jj = 0; jj < 4; jj++) {
            float4 v = p[jj];
            acc[jj][0] += v.x; acc[jj][1] += v.y; acc[jj][2] += v.z; acc[jj][3] += v.w;
        }
        const int row0 = m0 + wm * 16 + g;
        const int row1 = row0 + 8;
        #pragma unroll
        for (int jj = 0; jj < 4; jj++) {
            const int col = n0 + wn * 32 + jj * 8 + t4 * 2;
            float2 bb = *(const float2*)(bias + col);
            float v00 = fmaxf(acc[jj][0] + bb.x, 0.0f);
            float v01 = fmaxf(acc[jj][1] + bb.y, 0.0f);
            float v10 = fmaxf(acc[jj][2] + bb.x, 0.0f);
            float v11 = fmaxf(acc[jj][3] + bb.y, 0.0f);
            if (ext_next) {
                float2 e0 = *(const float2*)(ext_next + (size_t)row0 * SS + col);
                float2 e1 = *(const float2*)(ext_next + (size_t)row1 * SS + col);
                v00 += e0.x; v01 += e0.y; v10 += e1.x; v11 += e1.y;
            }
            __half h00 = __float2half_rn(v00), h01 = __float2half_rn(v01);
            __half h10 = __float2half_rn(v10), h11 = __float2half_rn(v11);
            __half l00 = __float2half_rn(v00 - __half2float(h00));
            __half l01 = __float2half_rn(v01 - __half2float(h01));
            __half l10 = __float2half_rn(v10 - __half2float(h10));
            __half l11 = __float2half_rn(v11 - __half2float(h11));
            *(uint32_t*)(Oh + (size_t)row0 * SS + col) =
                (uint32_t)__half_as_ushort(h00) | ((uint32_t)__half_as_ushort(h01) << 16);
            *(uint32_t*)(Oh + (size_t)row1 * SS + col) =
                (uint32_t)__half_as_ushort(h10) | ((uint32_t)__half_as_ushort(h11) << 16);
            *(uint32_t*)(Ol + (size_t)row0 * SS + col) =
                (uint32_t)__half_as_ushort(l00) | ((uint32_t)__half_as_ushort(l01) << 16);
            *(uint32_t*)(Ol + (size_t)row1 * SS + col) =
                (uint32_t)__half_as_ushort(l10) | ((uint32_t)__half_as_ushort(l11) << 16);
        }
    }
    // Allow the next layer's CTAs to schedule + prefetch weights.
    gdc_launch();
}

// ---------------- input projection (bf16 3-term MMA) ------------------------
#define PA_HI 0
#define PA_LO 16384
#define PB_HI 32768
#define PB_LO 49152
#define P_SM  65536

__global__ __launch_bounds__(256) void proj_mma(
    const __nv_bfloat16* __restrict__ Xh, const __nv_bfloat16* __restrict__ Xl,
    const __nv_bfloat16* __restrict__ Wh, const __nv_bfloat16* __restrict__ Wl,
    const float* __restrict__ bias, float* __restrict__ Out)
{
    extern __shared__ char smem[];
    const uint32_t sb = smem_u32(smem);
    const int tid = threadIdx.x;
    const int wid = tid >> 5, lane = tid & 31;
    const int g = lane >> 2, t4 = lane & 3;
    const int wm = (wid >> 1) << 4;
    const int wn = (wid & 1) << 5;
    const int m0 = blockIdx.x * 64, n0 = blockIdx.y * 64;

    #pragma unroll
    for (int i = 0; i < 16; i++) {
        int u = tid + (i << 8);
        const __nv_bfloat16* src;
        uint32_t dst;
        if (u < 2048) {
            int sel = u >> 10, v = u & 1023;
            int row = v >> 4, cu = v & 15;
            src = (sel ? Xl : Xh) + (size_t)(m0 + row) * IND + cu * 8;
            dst = sb + (sel ? PA_LO : PA_HI) + row * 256
                + (((cu & 8) | ((cu & 7) ^ (row & 7))) << 4);
        } else {
            int w = u - 2048;
            int sel = w >> 10, v = w & 1023;
            int row = v >> 4, cu = v & 15;
            src = (sel ? Wl : Wh) + (size_t)(n0 + row) * IND + cu * 8;
            dst = sb + (sel ? PB_LO : PB_HI) + row * 256
                + (((cu & 8) | ((cu & 7) ^ (row & 7))) << 4);
        }
        cp16(dst, src);
    }
    cp_commit();
    cp_wait0();
    __syncthreads();

    const int lr = lane & 7;
    const int half8 = (lane >> 3) & 1;
    const int khalf = (lane >> 4) & 1;
    const int rowA = wm + half8 * 8 + lr;
    const int rowB = wn + half8 * 8 + lr;
    const int swA = rowA & 7, swB = rowB & 7;

    float acc[4][4] = {};
    #pragma unroll
    for (int ks = 0; ks < 8; ks++) {
        const int u = ks * 2 + khalf;
        const uint32_t puA = (((u & 8) | ((u & 7) ^ swA)) << 4);
        const uint32_t puB = (((u & 8) | ((u & 7) ^ swB)) << 4);
        uint32_t ah[4], al[4];
        ldsm_x4(ah, sb + PA_HI + rowA * 256 + puA);
        ldsm_x4(al, sb + PA_LO + rowA * 256 + puA);
        #pragma unroll
        for (int jj = 0; jj < 2; jj++) {
            uint32_t bh[4], bl[4];
            ldsm_x4(bh, sb + PB_HI + (rowB + jj * 16) * 256 + puB);
            ldsm_x4(bl, sb + PB_LO + (rowB + jj * 16) * 256 + puB);
            mma_bf16(acc[jj * 2],     ah, bh[0], bh[2]);
            mma_bf16(acc[jj * 2],     ah, bl[0], bl[2]);
            mma_bf16(acc[jj * 2],     al, bh[0], bh[2]);
            mma_bf16(acc[jj * 2 + 1], ah, bh[1], bh[3]);
            mma_bf16(acc[jj * 2 + 1], ah, bl[1], bl[3]);
            mma_bf16(acc[jj * 2 + 1], al, bh[1], bh[3]);
        }
    }

    const int r0 = m0 + wm + g;
    const int r1 = r0 + 8;
    const int b0r = r0 >> 8, t0r = r0 & 255;
    const int b1r = r1 >> 8, t1r = r1 & 255;
    #pragma unroll
    for (int j = 0; j < 4; j++) {
        const int col = n0 + wn + j * 8 + t4 * 2;
        float2 bb = *(const float2*)(bias + col);
        float2 o0 = make_float2(acc[j][0] + bb.x, acc[j][1] + bb.y);
        float2 o1 = make_float2(acc[j][2] + bb.x, acc[j][3] + bb.y);
        *(float2*)(Out + ((size_t)t0r * BB + b0r) * SS + col) = o0;
        *(float2*)(Out + ((size_t)t1r * BB + b1r) * SS + col) = o1;
    }
}

// ---------------- conversion kernels ----------------------------------------
__global__ void splitBF_kernel(const float4* __restrict__ in,
                               uint2* __restrict__ hi, uint2* __restrict__ lo, int n4)
{
    int i = blockIdx.x * blockDim.x + threadIdx.x;
    if (i >= n4) return;
    float4 v = in[i];
    __nv_bfloat16 h0 = __float2bfloat16(v.x), h1 = __float2bfloat16(v.y);
    __nv_bfloat16 h2 = __float2bfloat16(v.z), h3 = __float2bfloat16(v.w);
    __nv_bfloat16 l0 = __float2bfloat16(v.x - __bfloat162float(h0));
    __nv_bfloat16 l1 = __float2bfloat16(v.y - __bfloat162float(h1));
    __nv_bfloat16 l2 = __float2bfloat16(v.z - __bfloat162float(h2));
    __nv_bfloat16 l3 = __float2bfloat16(v.w - __bfloat162float(h3));
    uint2 H, L;
    H.x = (uint32_t)__bfloat16_as_ushort(h0) | ((uint32_t)__bfloat16_as_ushort(h1) << 16);
    H.y = (uint32_t)__bfloat16_as_ushort(h2) | ((uint32_t)__bfloat16_as_ushort(h3) << 16);
    L.x = (uint32_t)__bfloat16_as_ushort(l0) | ((uint32_t)__bfloat16_as_ushort(l1) << 16);
    L.y = (uint32_t)__bfloat16_as_ushort(l2) | ((uint32_t)__bfloat16_as_ushort(l3) << 16);
    hi[i] = H; lo[i] = L;
}

__global__ void splitH_kernel(const float4* __restrict__ in,
                              uint2* __restrict__ hi, uint2* __restrict__ lo, int n4)
{
    int i = blockIdx.x * blockDim.x + threadIdx.x;
    if (i >= n4) return;
    float4 v = in[i];
    __half h0 = __float2half_rn(v.x), h1 = __float2half_rn(v.y);
    __half h2 = __float2half_rn(v.z), h3 = __float2half_rn(v.w);
    __half l0 = __float2half_rn(v.x - __half2float(h0));
    __half l1 = __float2half_rn(v.y - __half2float(h1));
    __half l2 = __float2half_rn(v.z - __half2float(h2));
    __half l3 = __float2half_rn(v.w - __half2float(h3));
    uint2 H, L;
    H.x = (uint32_t)__half_as_ushort(h0) | ((uint32_t)__half_as_ushort(h1) << 16);
    H.y = (uint32_t)__half_as_ushort(h2) | ((uint32_t)__half_as_ushort(h3) << 16);
    L.x = (uint32_t)__half_as_ushort(l0) | ((uint32_t)__half_as_ushort(l1) << 16);
    L.y = (uint32_t)__half_as_ushort(l2) | ((uint32_t)__half_as_ushort(l3) << 16);
    hi[i] = H; lo[i] = L;
}

__global__ void convH_kernel(const float4* __restrict__ in, uint2* __restrict__ out, int n4)
{
    int i = blockIdx.x * blockDim.x + threadIdx.x;
    if (i >= n4) return;
    float4 v = in[i];
    uint2 O;
    O.x = (uint32_t)__half_as_ushort(__float2half_rn(v.x))
        | ((uint32_t)__half_as_ushort(__float2half_rn(v.y)) << 16);
    O.y = (uint32_t)__half_as_ushort(__float2half_rn(v.z))
        | ((uint32_t)__half_as_ushort(__float2half_rn(v.w)) << 16);
    out[i] = O;
}

__global__ void bcastH_kernel(const uint2* __restrict__ hi, const uint2* __restrict__ lo,
                              float4* __restrict__ out)
{
    int i = blockIdx.x * blockDim.x + threadIdx.x;
    int b  = i >> 16;
    int s4 = i & 255;
    uint2 H = hi[(b << 8) + s4];
    uint2 L = lo[(b << 8) + s4];
    float4 o;
    o.x = __half2float(__ushort_as_half((unsigned short)(H.x & 0xFFFF)))
        + __half2float(__ushort_as_half((unsigned short)(L.x & 0xFFFF)));
    o.y = __half2float(__ushort_as_half((unsigned short)(H.x >> 16)))
        + __half2float(__ushort_as_half((unsigned short)(L.x >> 16)));
    o.z = __half2float(__ushort_as_half((unsigned short)(H.y & 0xFFFF)))
        + __half2float(__ushort_as_half((unsigned short)(L.y & 0xFFFF)));
    o.w = __half2float(__ushort_as_half((unsigned short)(H.y >> 16)))
        + __half2float(__ushort_as_half((unsigned short)(L.y >> 16)));
    out[i] = o;
}

// ---------------- driver ----------------------------------------------------
extern "C" void kernel_launch(void* const* d_in, const int* in_sizes, int n_in,
                              void* d_out, int out_size)
{
    const float* x      = (const float*)d_in[0];
    const float* W_in   = (const float*)d_in[1];
    const float* b_in   = (const float*)d_in[2];
    const float* W_rec  = (const float*)d_in[3];
    const float* b_rec  = (const float*)d_in[4];
    const float* W_rec2 = (const float*)d_in[5];
    const float* b_rec2 = (const float*)d_in[6];
    float* out = (float*)d_out;

    float* ext;
    __half *sAh, *sAl, *sBh, *sBl, *W1, *W2;
    __nv_bfloat16 *xh, *xl, *Winh, *Winl;
    cudaGetSymbolAddress((void**)&ext, g_ext);
    cudaGetSymbolAddress((void**)&sAh, g_sAh);
    cudaGetSymbolAddress((void**)&sAl, g_sAl);
    cudaGetSymbolAddress((void**)&sBh, g_sBh);
    cudaGetSymbolAddress((void**)&sBl, g_sBl);
    cudaGetSymbolAddress((void**)&W1,  g_W1);
    cudaGetSymbolAddress((void**)&W2,  g_W2);
    cudaGetSymbolAddress((void**)&xh,  g_xh);
    cudaGetSymbolAddress((void**)&xl,  g_xl);
    cudaGetSymbolAddress((void**)&Winh, g_Winh);
    cudaGetSymbolAddress((void**)&Winl, g_Winl);

    cudaFuncSetAttribute(layer_kernel, cudaFuncAttributeMaxDynamicSharedMemorySize, SM_TOTAL);
    cudaFuncSetAttribute(proj_mma,     cudaFuncAttributeMaxDynamicSharedMemorySize, P_SM);

    // weights -> fp16
    convH_kernel<<<(SS * SS / 4) / 256, 256>>>((const float4*)W_rec,  (uint2*)W1, SS * SS / 4);
    convH_kernel<<<(SS * SS / 4) / 256, 256>>>((const float4*)W_rec2, (uint2*)W2, SS * SS / 4);

    // x, W_in -> bf16 hi/lo for projection
    splitBF_kernel<<<((size_t)BB * TT * IND / 4 + 255) / 256, 256>>>(
        (const float4*)x, (uint2*)xh, (uint2*)xl, BB * TT * IND / 4);
    splitBF_kernel<<<(SS * IND / 4 + 255) / 256, 256>>>(
        (const float4*)W_in, (uint2*)Winh, (uint2*)Winl, SS * IND / 4);

    // Phase 1: ext = x @ W_in^T + b_in
    {
        dim3 grid((BB * TT) / 64, SS / 64);
        proj_mma<<<grid, 256, P_SM>>>(xh, xl, Winh, Winl, b_in, ext);
    }

    // Initial state: s0 = 0 + ext[0] -> fp16 hi/lo
    splitH_kernel<<<(BB * SS / 4) / 256, 256>>>((const float4*)ext, (uint2*)sAh, (uint2*)sAl, BB * SS / 4);

    // Phase 2: 256 steps x 2 layers, PDL-chained launches
    {
        cudaLaunchConfig_t cfg = {};
        cfg.gridDim  = dim3(BB / M_TILE, SS / N_TILE, 1);   // (8, 16) = 128 CTAs
        cfg.blockDim = dim3(256, 1, 1);
        cfg.dynamicSmemBytes = SM_TOTAL;
        cudaLaunchAttribute at[1];
        at[0].id = cudaLaunchAttributeProgrammaticStreamSerialization;
        at[0].val.programmaticStreamSerializationAllowed = 1;
        cfg.attrs = at;
        cfg.numAttrs = 1;

        const float* nil = nullptr;
        for (int t = 0; t < TT; t++) {
            if (cudaLaunchKernelEx(&cfg, layer_kernel,
                    (const __half*)sAh, (const __half*)sAl, (const __half*)W1,
                    (const float*)b_rec, nil, sBh, sBl) != cudaSuccess)
                layer_kernel<<<cfg.gridDim, cfg.blockDim, SM_TOTAL>>>(
                    sAh, sAl, W1, b_rec, nullptr, sBh, sBl);
            const float* en = (t + 1 < TT) ? ext + (size_t)(t + 1) * BB * SS : nullptr;
            if (cudaLaunchKernelEx(&cfg, layer_kernel,
                    (const __half*)sBh, (const __half*)sBl, (const __half*)W2,
                    (const float*)b_rec2, en, sAh, sAl) != cudaSuccess)
                layer_kernel<<<cfg.gridDim, cfg.blockDim, SM_TOTAL>>>(
                    sBh, sBl, W2, b_rec2, en, sAh, sAl);
        }
    }

    // Phase 3: broadcast final state (normal launch: full serialization)
    bcastH_kernel<<<(BB * TT * SS / 4) / 256, 256>>>((const uint2*)sAh, (const uint2*)sAl, (float4*)out);
}

// round 8
// speedup vs baseline: 1.8358x; 1.0520x over previous
#include <cuda_runtime.h>
#include <cuda_bf16.h>
#include <cuda_fp16.h>
#include <cstdint>

// Problem dims
#define BB  256
#define TT  256
#define IND 128
#define SS  1024

// ---------------- scratch (__device__ globals) ------------------------------
__device__ float g_ext[(size_t)TT * BB * SS];            // [t][b][s] fp32
__device__ __half g_sAh[BB * SS], g_sAl[BB * SS];        // state hi/lo fp16
__device__ __half g_sBh[BB * SS], g_sBl[BB * SS];
__device__ __half g_W1[SS * SS], g_W2[SS * SS];          // weights plain fp16
__device__ __nv_bfloat16 g_xh[(size_t)BB * TT * IND], g_xl[(size_t)BB * TT * IND];
__device__ __nv_bfloat16 g_Winh[SS * IND], g_Winl[SS * IND];

// ---------------- helpers ---------------------------------------------------
__device__ __forceinline__ uint32_t smem_u32(const void* p) {
    uint32_t a;
    asm("{ .reg .u64 t; cvta.to.shared.u64 t, %1; cvt.u32.u64 %0, t; }" : "=r"(a) : "l"(p));
    return a;
}
__device__ __forceinline__ void cp16(uint32_t dst, const void* src) {
    asm volatile("cp.async.cg.shared.global [%0], [%1], 16;" :: "r"(dst), "l"(src));
}
__device__ __forceinline__ void cp_commit() { asm volatile("cp.async.commit_group;"); }
__device__ __forceinline__ void cp_wait0()  { asm volatile("cp.async.wait_group 0;"); }
__device__ __forceinline__ void cp_wait1()  { asm volatile("cp.async.wait_group 1;"); }
__device__ __forceinline__ void gdc_wait()   { asm volatile("griddepcontrol.wait;" ::: "memory"); }
__device__ __forceinline__ void gdc_launch() { asm volatile("griddepcontrol.launch_dependents;"); }

__device__ __forceinline__ void mma_bf16(float* c, const uint32_t* a,
                                         uint32_t b0, uint32_t b1) {
    asm volatile(
        "mma.sync.aligned.m16n8k16.row.col.f32.bf16.bf16.f32 "
        "{%0,%1,%2,%3}, {%4,%5,%6,%7}, {%8,%9}, {%0,%1,%2,%3};"
        : "+f"(c[0]), "+f"(c[1]), "+f"(c[2]), "+f"(c[3])
        : "r"(a[0]), "r"(a[1]), "r"(a[2]), "r"(a[3]), "r"(b0), "r"(b1));
}
__device__ __forceinline__ void mma_f16(float* c, const uint32_t* a,
                                        uint32_t b0, uint32_t b1) {
    asm volatile(
        "mma.sync.aligned.m16n8k16.row.col.f32.f16.f16.f32 "
        "{%0,%1,%2,%3}, {%4,%5,%6,%7}, {%8,%9}, {%0,%1,%2,%3};"
        : "+f"(c[0]), "+f"(c[1]), "+f"(c[2]), "+f"(c[3])
        : "r"(a[0]), "r"(a[1]), "r"(a[2]), "r"(a[3]), "r"(b0), "r"(b1));
}
__device__ __forceinline__ void ldsm_x4(uint32_t* r, uint32_t addr) {
    asm volatile("ldmatrix.sync.aligned.m8n8.x4.shared.b16 {%0,%1,%2,%3}, [%4];"
                 : "=r"(r[0]), "=r"(r[1]), "=r"(r[2]), "=r"(r[3]) : "r"(addr));
}

// ---------------- layer GEMM (fp16 2-term, 3-stage, single sync, PDL) -------
// O = relu((Ah+Al) @ W^T + bias) (+ ext_next). CTA tile 32x64, KC=64.
// 8 warps (wm2 x wn2 x kslot2), warp tile 16x32, K split across kslot;
// cross-warp pair reduction via SMEM. Stages: 3 x 16KB {A hi 4K, A lo 4K, B 8K}.
// One __syncthreads per chunk; uniform cp.async.wait_group 1.
// B stages 0,1 prefetched BEFORE griddepcontrol.wait (weights are static).
#define M_TILE 32
#define N_TILE 64
#define KC     64
#define NCHUNK (SS / KC)          // 16
#define STG    16384
#define SB_ALO 4096
#define SB_B   8192
#define SM_TOTAL (3 * STG)        // 49152

__device__ __forceinline__ void load_A(uint32_t st, int kc0, int tid, int m0,
    const __half* __restrict__ Ah, const __half* __restrict__ Al)
{
    #pragma unroll
    for (int i = 0; i < 2; i++) {
        int u = tid + (i << 8);          // 0..511
        int sel = u >> 8;                // 0 hi, 1 lo
        int v = u & 255;
        int row = v >> 3, cu = v & 7;
        const __half* src = (sel ? Al : Ah) + (size_t)(m0 + row) * SS + kc0 + cu * 8;
        cp16(st + (sel ? SB_ALO : 0) + row * 128 + ((cu ^ (row & 7)) << 4), src);
    }
}
__device__ __forceinline__ void load_B(uint32_t st, int kc0, int tid, int n0,
    const __half* __restrict__ W)
{
    #pragma unroll
    for (int i = 0; i < 2; i++) {
        int u = tid + (i << 8);          // 0..511
        int row = u >> 3, cu = u & 7;    // 64 rows x 8 units
        const __half* src = W + (size_t)(n0 + row) * SS + kc0 + cu * 8;
        cp16(st + SB_B + row * 128 + ((cu ^ (row & 7)) << 4), src);
    }
}

__global__ __launch_bounds__(256) void layer_kernel(
    const __half* __restrict__ Ah, const __half* __restrict__ Al,
    const __half* __restrict__ W,
    const float* __restrict__ bias, const float* __restrict__ ext_next,
    __half* __restrict__ Oh, __half* __restrict__ Ol)
{
    extern __shared__ char smem[];
    const uint32_t sb = smem_u32(smem);
    const int tid = threadIdx.x;
    const int wid = tid >> 5, lane = tid & 31;
    const int g = lane >> 2, t4 = lane & 3;
    const int wm = (wid >> 2) & 1;       // rows wm*16
    const int wn = (wid >> 1) & 1;       // cols wn*32
    const int kslot = wid & 1;           // K half
    const int m0 = blockIdx.x * M_TILE, n0 = blockIdx.y * N_TILE;

    const int lr = lane & 7;
    const int half8 = (lane >> 3) & 1;
    const int khalf = (lane >> 4) & 1;
    const int rowA  = wm * 16 + half8 * 8 + lr;
    const int rowB0 = wn * 32 + half8 * 8 + lr;
    const int rowB1 = rowB0 + 16;
    const int swA = rowA & 7, swB0 = rowB0 & 7, swB1 = rowB1 & 7;

    // Prefetch weight stages 0,1 BEFORE the grid dependency (W is static).
    load_B(sb, 0, tid, n0, W);              cp_commit();   // g0 = B0
    load_B(sb + STG, KC, tid, n0, W);       cp_commit();   // g1 = B1
    gdc_wait();                                            // prev layer done
    load_A(sb, 0, tid, m0, Ah, Al);         cp_commit();   // g2 = A0
    load_A(sb + STG, KC, tid, m0, Ah, Al);  cp_commit();   // g3 = A1

    float acc[4][4] = {};
    int st_c = 0, st_p = 2;   // stage of chunk c, stage of chunk c+2

    #pragma unroll 1
    for (int c = 0; c < NCHUNK; c++) {
        if (c < NCHUNK - 1) cp_wait1(); else cp_wait0();
        __syncthreads();
        if (c + 2 < NCHUNK) {
            const uint32_t sp = sb + st_p * STG;
            load_A(sp, (c + 2) * KC, tid, m0, Ah, Al);
            load_B(sp, (c + 2) * KC, tid, n0, W);
            cp_commit();                                   // g_{c+4}
        }

        const uint32_t aBase = sb + st_c * STG;
        const uint32_t bBase = aBase + SB_B;
        #pragma unroll
        for (int k2 = 0; k2 < 2; k2++) {
            const int u = (kslot * 2 + k2) * 2 + khalf;
            uint32_t ah[4], al[4], b0[4], b1[4];
            ldsm_x4(ah, aBase + rowA * 128 + ((u ^ swA) << 4));
            ldsm_x4(al, aBase + SB_ALO + rowA * 128 + ((u ^ swA) << 4));
            ldsm_x4(b0, bBase + rowB0 * 128 + ((u ^ swB0) << 4));
            ldsm_x4(b1, bBase + rowB1 * 128 + ((u ^ swB1) << 4));
            mma_f16(acc[0], ah, b0[0], b0[2]);
            mma_f16(acc[1], ah, b0[1], b0[3]);
            mma_f16(acc[2], ah, b1[0], b1[2]);
            mma_f16(acc[3], ah, b1[1], b1[3]);
            mma_f16(acc[0], al, b0[0], b0[2]);
            mma_f16(acc[1], al, b0[1], b0[3]);
            mma_f16(acc[2], al, b1[0], b1[2]);
            mma_f16(acc[3], al, b1[1], b1[3]);
        }
        st_c = (st_c == 2) ? 0 : st_c + 1;
        st_p = (st_p == 2) ? 0 : st_p + 1;
    }
    __syncthreads();   // all warps done with last stage before scratch overlay

    // Cross-warp K reduction (scratch overlays stage 0).
    float* scr = (float*)smem;
    const int pair = wid >> 1;               // 0..3 = (wm,wn)
    if (kslot == 1) {
        float4* p = (float4*)(scr + pair * 512 + lane * 16);
        #pragma unroll
        for (int jj = 0; jj < 4; jj++)
            p[jj] = make_float4(acc[jj][0], acc[jj][1], acc[jj][2], acc[jj][3]);
    }
    __syncthreads();
    if (kslot == 0) {
        const float4* p = (const float4*)(scr + pair * 512 + lane * 16);
        #pragma unroll
        for (int jj = 0; jj < 4; jj++) {
            float4 v = p[jj];
            acc[jj][0] += v.x; acc[jj][1] += v.y; acc[jj][2] += v.z; acc[jj][3] += v.w;
        }
        const int row0 = m0 + wm * 16 + g;
        const int row1 = row0 + 8;
        #pragma unroll
        for (int jj = 0; jj < 4; jj++) {
            const int col = n0 + wn * 32 + jj * 8 + t4 * 2;
            float2 bb = *(const float2*)(bias + col);
            float v00 = fmaxf(acc[jj][0] + bb.x, 0.0f);
            float v01 = fmaxf(acc[jj][1] + bb.y, 0.0f);
            float v10 = fmaxf(acc[jj][2] + bb.x, 0.0f);
            float v11 = fmaxf(acc[jj][3] + bb.y, 0.0f);
            if (ext_next) {
                float2 e0 = *(const float2*)(ext_next + (size_t)row0 * SS + col);
                float2 e1 = *(const float2*)(ext_next + (size_t)row1 * SS + col);
                v00 += e0.x; v01 += e0.y; v10 += e1.x; v11 += e1.y;
            }
            __half h00 = __float2half_rn(v00), h01 = __float2half_rn(v01);
            __half h10 = __float2half_rn(v10), h11 = __float2half_rn(v11);
            __half l00 = __float2half_rn(v00 - __half2float(h00));
            __half l01 = __float2half_rn(v01 - __half2float(h01));
            __half l10 = __float2half_rn(v10 - __half2float(h10));
            __half l11 = __float2half_rn(v11 - __half2float(h11));
            *(uint32_t*)(Oh + (size_t)row0 * SS + col) =
                (uint32_t)__half_as_ushort(h00) | ((uint32_t)__half_as_ushort(h01) << 16);
            *(uint32_t*)(Oh + (size_t)row1 * SS + col) =
                (uint32_t)__half_as_ushort(h10) | ((uint32_t)__half_as_ushort(h11) << 16);
            *(uint32_t*)(Ol + (size_t)row0 * SS + col) =
                (uint32_t)__half_as_ushort(l00) | ((uint32_t)__half_as_ushort(l01) << 16);
            *(uint32_t*)(Ol + (size_t)row1 * SS + col) =
                (uint32_t)__half_as_ushort(l10) | ((uint32_t)__half_as_ushort(l11) << 16);
        }
    }
    gdc_launch();
}

// ---------------- input projection (bf16 3-term MMA; also writes s0) --------
#define PA_HI 0
#define PA_LO 16384
#define PB_HI 32768
#define PB_LO 49152
#define P_SM  65536

__global__ __launch_bounds__(256) void proj_mma(
    const __nv_bfloat16* __restrict__ Xh, const __nv_bfloat16* __restrict__ Xl,
    const __nv_bfloat16* __restrict__ Wh, const __nv_bfloat16* __restrict__ Wl,
    const float* __restrict__ bias, float* __restrict__ Out,
    __half* __restrict__ S0h, __half* __restrict__ S0l)
{
    extern __shared__ char smem[];
    const uint32_t sb = smem_u32(smem);
    const int tid = threadIdx.x;
    const int wid = tid >> 5, lane = tid & 31;
    const int g = lane >> 2, t4 = lane & 3;
    const int wm = (wid >> 1) << 4;
    const int wn = (wid & 1) << 5;
    const int m0 = blockIdx.x * 64, n0 = blockIdx.y * 64;

    #pragma unroll
    for (int i = 0; i < 16; i++) {
        int u = tid + (i << 8);
        const __nv_bfloat16* src;
        uint32_t dst;
        if (u < 2048) {
            int sel = u >> 10, v = u & 1023;
            int row = v >> 4, cu = v & 15;
            src = (sel ? Xl : Xh) + (size_t)(m0 + row) * IND + cu * 8;
            dst = sb + (sel ? PA_LO : PA_HI) + row * 256
                + (((cu & 8) | ((cu & 7) ^ (row & 7))) << 4);
        } else {
            int w = u - 2048;
            int sel = w >> 10, v = w & 1023;
            int row = v >> 4, cu = v & 15;
            src = (sel ? Wl : Wh) + (size_t)(n0 + row) * IND + cu * 8;
            dst = sb + (sel ? PB_LO : PB_HI) + row * 256
                + (((cu & 8) | ((cu & 7) ^ (row & 7))) << 4);
        }
        cp16(dst, src);
    }
    cp_commit();
    cp_wait0();
    __syncthreads();

    const int lr = lane & 7;
    const int half8 = (lane >> 3) & 1;
    const int khalf = (lane >> 4) & 1;
    const int rowA = wm + half8 * 8 + lr;
    const int rowB = wn + half8 * 8 + lr;
    const int swA = rowA & 7, swB = rowB & 7;

    float acc[4][4] = {};
    #pragma unroll
    for (int ks = 0; ks < 8; ks++) {
        const int u = ks * 2 + khalf;
        const uint32_t puA = (((u & 8) | ((u & 7) ^ swA)) << 4);
        const uint32_t puB = (((u & 8) | ((u & 7) ^ swB)) << 4);
        uint32_t ah[4], al[4];
        ldsm_x4(ah, sb + PA_HI + rowA * 256 + puA);
        ldsm_x4(al, sb + PA_LO + rowA * 256 + puA);
        #pragma unroll
        for (int jj = 0; jj < 2; jj++) {
            uint32_t bh[4], bl[4];
            ldsm_x4(bh, sb + PB_HI + (rowB + jj * 16) * 256 + puB);
            ldsm_x4(bl, sb + PB_LO + (rowB + jj * 16) * 256 + puB);
            mma_bf16(acc[jj * 2],     ah, bh[0], bh[2]);
            mma_bf16(acc[jj * 2],     ah, bl[0], bl[2]);
            mma_bf16(acc[jj * 2],     al, bh[0], bh[2]);
            mma_bf16(acc[jj * 2 + 1], ah, bh[1], bh[3]);
            mma_bf16(acc[jj * 2 + 1], ah, bl[1], bl[3]);
            mma_bf16(acc[jj * 2 + 1], al, bh[1], bh[3]);
        }
    }

    const int r0 = m0 + wm + g;
    const int r1 = r0 + 8;
    const int b0r = r0 >> 8, t0r = r0 & 255;
    const int b1r = r1 >> 8, t1r = r1 & 255;
    #pragma unroll
    for (int j = 0; j < 4; j++) {
        const int col = n0 + wn + j * 8 + t4 * 2;
        float2 bb = *(const float2*)(bias + col);
        float2 o0 = make_float2(acc[j][0] + bb.x, acc[j][1] + bb.y);
        float2 o1 = make_float2(acc[j][2] + bb.x, acc[j][3] + bb.y);
        *(float2*)(Out + ((size_t)t0r * BB + b0r) * SS + col) = o0;
        *(float2*)(Out + ((size_t)t1r * BB + b1r) * SS + col) = o1;
        if (t0r == 0) {       // s0 = ext[0] in fp16 hi/lo (t1r==t0r+8 never 0)
            __half h0 = __float2half_rn(o0.x), h1 = __float2half_rn(o0.y);
            __half l0 = __float2half_rn(o0.x - __half2float(h0));
            __half l1 = __float2half_rn(o0.y - __half2float(h1));
            *(uint32_t*)(S0h + (size_t)b0r * SS + col) =
                (uint32_t)__half_as_ushort(h0) | ((uint32_t)__half_as_ushort(h1) << 16);
            *(uint32_t*)(S0l + (size_t)b0r * SS + col) =
                (uint32_t)__half_as_ushort(l0) | ((uint32_t)__half_as_ushort(l1) << 16);
        }
    }
}

// ---------------- fused prolog: all conversions in ONE launch ----------------
#define N_W   (SS * SS / 4)                    // 262144 per weight
#define N_X   ((size_t)BB * TT * IND / 4)      // 2097152
#define N_WIN (SS * IND / 4)                   // 32768
#define N_TOT (2 * N_W + (int)N_X + N_WIN)     // 2654208

__global__ void prep_kernel(
    const float4* __restrict__ Wr1, const float4* __restrict__ Wr2,
    const float4* __restrict__ X,   const float4* __restrict__ Win,
    uint2* __restrict__ W1, uint2* __restrict__ W2,
    uint2* __restrict__ xh, uint2* __restrict__ xl,
    uint2* __restrict__ wih, uint2* __restrict__ wil)
{
    int i = blockIdx.x * blockDim.x + threadIdx.x;
    if (i >= N_TOT) return;
    if (i < 2 * N_W) {                       // weight -> fp16 convert
        const float4* src = (i < N_W) ? Wr1 : Wr2;
        uint2* dst        = (i < N_W) ? W1  : W2;
        int k = (i < N_W) ? i : i - N_W;
        float4 v = src[k];
        uint2 O;
        O.x = (uint32_t)__half_as_ushort(__float2half_rn(v.x))
            | ((uint32_t)__half_as_ushort(__float2half_rn(v.y)) << 16);
        O.y = (uint32_t)__half_as_ushort(__float2half_rn(v.z))
            | ((uint32_t)__half_as_ushort(__float2half_rn(v.w)) << 16);
        dst[k] = O;
    } else {                                 // bf16 hi/lo split (x or W_in)
        int k = i - 2 * N_W;
        const float4* src; uint2 *dh, *dl;
        if (k < (int)N_X) { src = X; dh = xh; dl = xl; }
        else { k -= (int)N_X; src = Win; dh = wih; dl = wil; }
        float4 v = src[k];
        __nv_bfloat16 h0 = __float2bfloat16(v.x), h1 = __float2bfloat16(v.y);
        __nv_bfloat16 h2 = __float2bfloat16(v.z), h3 = __float2bfloat16(v.w);
        __nv_bfloat16 l0 = __float2bfloat16(v.x - __bfloat162float(h0));
        __nv_bfloat16 l1 = __float2bfloat16(v.y - __bfloat162float(h1));
        __nv_bfloat16 l2 = __float2bfloat16(v.z - __bfloat162float(h2));
        __nv_bfloat16 l3 = __float2bfloat16(v.w - __bfloat162float(h3));
        uint2 H, L;
        H.x = (uint32_t)__bfloat16_as_ushort(h0) | ((uint32_t)__bfloat16_as_ushort(h1) << 16);
        H.y = (uint32_t)__bfloat16_as_ushort(h2) | ((uint32_t)__bfloat16_as_ushort(h3) << 16);
        L.x = (uint32_t)__bfloat16_as_ushort(l0) | ((uint32_t)__bfloat16_as_ushort(l1) << 16);
        L.y = (uint32_t)__bfloat16_as_ushort(l2) | ((uint32_t)__bfloat16_as_ushort(l3) << 16);
        dh[k] = H; dl[k] = L;
    }
}

// ---------------- broadcast final state (fp16 hi+lo -> fp32) ----------------
__global__ void bcastH_kernel(const uint2* __restrict__ hi, const uint2* __restrict__ lo,
                              float4* __restrict__ out)
{
    int i = blockIdx.x * blockDim.x + threadIdx.x;
    int b  = i >> 16;
    int s4 = i & 255;
    uint2 H = hi[(b << 8) + s4];
    uint2 L = lo[(b << 8) + s4];
    float4 o;
    o.x = __half2float(__ushort_as_half((unsigned short)(H.x & 0xFFFF)))
        + __half2float(__ushort_as_half((unsigned short)(L.x & 0xFFFF)));
    o.y = __half2float(__ushort_as_half((unsigned short)(H.x >> 16)))
        + __half2float(__ushort_as_half((unsigned short)(L.x >> 16)));
    o.z = __half2float(__ushort_as_half((unsigned short)(H.y & 0xFFFF)))
        + __half2float(__ushort_as_half((unsigned short)(L.y & 0xFFFF)));
    o.w = __half2float(__ushort_as_half((unsigned short)(H.y >> 16)))
        + __half2float(__ushort_as_half((unsigned short)(L.y >> 16)));
    out[i] = o;
}

// ---------------- driver ----------------------------------------------------
extern "C" void kernel_launch(void* const* d_in, const int* in_sizes, int n_in,
                              void* d_out, int out_size)
{
    const float* x      = (const float*)d_in[0];
    const float* W_in   = (const float*)d_in[1];
    const float* b_in   = (const float*)d_in[2];
    const float* W_rec  = (const float*)d_in[3];
    const float* b_rec  = (const float*)d_in[4];
    const float* W_rec2 = (const float*)d_in[5];
    const float* b_rec2 = (const float*)d_in[6];
    float* out = (float*)d_out;

    float* ext;
    __half *sAh, *sAl, *sBh, *sBl, *W1, *W2;
    __nv_bfloat16 *xh, *xl, *Winh, *Winl;
    cudaGetSymbolAddress((void**)&ext, g_ext);
    cudaGetSymbolAddress((void**)&sAh, g_sAh);
    cudaGetSymbolAddress((void**)&sAl, g_sAl);
    cudaGetSymbolAddress((void**)&sBh, g_sBh);
    cudaGetSymbolAddress((void**)&sBl, g_sBl);
    cudaGetSymbolAddress((void**)&W1,  g_W1);
    cudaGetSymbolAddress((void**)&W2,  g_W2);
    cudaGetSymbolAddress((void**)&xh,  g_xh);
    cudaGetSymbolAddress((void**)&xl,  g_xl);
    cudaGetSymbolAddress((void**)&Winh, g_Winh);
    cudaGetSymbolAddress((void**)&Winl, g_Winl);

    cudaFuncSetAttribute(layer_kernel, cudaFuncAttributeMaxDynamicSharedMemorySize, SM_TOTAL);
    cudaFuncSetAttribute(proj_mma,     cudaFuncAttributeMaxDynamicSharedMemorySize, P_SM);

    // Launch 0: fused prolog (weights fp16, x/W_in bf16 hi/lo)
    prep_kernel<<<(N_TOT + 255) / 256, 256>>>(
        (const float4*)W_rec, (const float4*)W_rec2,
        (const float4*)x, (const float4*)W_in,
        (uint2*)W1, (uint2*)W2, (uint2*)xh, (uint2*)xl, (uint2*)Winh, (uint2*)Winl);

    // Launch 1: ext = x @ W_in^T + b_in; also writes s0 = ext[0] hi/lo
    {
        dim3 grid((BB * TT) / 64, SS / 64);
        proj_mma<<<grid, 256, P_SM>>>(xh, xl, Winh, Winl, b_in, ext, sAh, sAl);
    }

    // Launches 2..513: scan, PDL-chained
    {
        cudaLaunchConfig_t cfg = {};
        cfg.gridDim  = dim3(BB / M_TILE, SS / N_TILE, 1);   // (8, 16) = 128 CTAs
        cfg.blockDim = dim3(256, 1, 1);
        cfg.dynamicSmemBytes = SM_TOTAL;
        cudaLaunchAttribute at[1];
        at[0].id = cudaLaunchAttributeProgrammaticStreamSerialization;
        at[0].val.programmaticStreamSerializationAllowed = 1;
        cfg.attrs = at;
        cfg.numAttrs = 1;

        const float* nil = nullptr;
        for (int t = 0; t < TT; t++) {
            if (cudaLaunchKernelEx(&cfg, layer_kernel,
                    (const __half*)sAh, (const __half*)sAl, (const __half*)W1,
                    (const float*)b_rec, nil, sBh, sBl) != cudaSuccess)
                layer_kernel<<<cfg.gridDim, cfg.blockDim, SM_TOTAL>>>(
                    sAh, sAl, W1, b_rec, nullptr, sBh, sBl);
            const float* en = (t + 1 < TT) ? ext + (size_t)(t + 1) * BB * SS : nullptr;
            if (cudaLaunchKernelEx(&cfg, layer_kernel,
                    (const __half*)sBh, (const __half*)sBl, (const __half*)W2,
                    (const float*)b_rec2, en, sAh, sAl) != cudaSuccess)
                layer_kernel<<<cfg.gridDim, cfg.blockDim, SM_TOTAL>>>(
                    sBh, sBl, W2, b_rec2, en, sAh, sAl);
        }
    }

    // Final: broadcast final state
    bcastH_kernel<<<(BB * TT * SS / 4) / 256, 256>>>((const uint2*)sAh, (const uint2*)sAl, (float4*)out);
}

// round 9
// speedup vs baseline: 1.9120x; 1.0415x over previous
#include <cuda_runtime.h>
#include <cuda_bf16.h>
#include <cuda_fp16.h>
#include <cstdint>

// Problem dims
#define BB  256
#define TT  256
#define IND 128
#define SS  1024

// ---------------- scratch (__device__ globals) ------------------------------
__device__ float g_ext[(size_t)TT * BB * SS];            // [t][b][s] fp32
__device__ __half g_sAh[BB * SS], g_sAl[BB * SS];        // state hi/lo fp16
__device__ __half g_sBh[BB * SS], g_sBl[BB * SS];
__device__ __half g_W1[SS * SS], g_W2[SS * SS];          // weights plain fp16
__device__ __nv_bfloat16 g_xh[(size_t)BB * TT * IND], g_xl[(size_t)BB * TT * IND];
__device__ __nv_bfloat16 g_Winh[SS * IND], g_Winl[SS * IND];

// ---------------- helpers ---------------------------------------------------
__device__ __forceinline__ uint32_t smem_u32(const void* p) {
    uint32_t a;
    asm("{ .reg .u64 t; cvta.to.shared.u64 t, %1; cvt.u32.u64 %0, t; }" : "=r"(a) : "l"(p));
    return a;
}
__device__ __forceinline__ void cp16(uint32_t dst, const void* src) {
    asm volatile("cp.async.cg.shared.global [%0], [%1], 16;" :: "r"(dst), "l"(src));
}
__device__ __forceinline__ void cp_commit() { asm volatile("cp.async.commit_group;"); }
__device__ __forceinline__ void cp_wait0()  { asm volatile("cp.async.wait_group 0;"); }
__device__ __forceinline__ void cp_wait1()  { asm volatile("cp.async.wait_group 1;"); }
__device__ __forceinline__ void gdc_wait()   { asm volatile("griddepcontrol.wait;" ::: "memory"); }
__device__ __forceinline__ void gdc_launch() { asm volatile("griddepcontrol.launch_dependents;"); }

__device__ __forceinline__ void mma_bf16(float* c, const uint32_t* a,
                                         uint32_t b0, uint32_t b1) {
    asm volatile(
        "mma.sync.aligned.m16n8k16.row.col.f32.bf16.bf16.f32 "
        "{%0,%1,%2,%3}, {%4,%5,%6,%7}, {%8,%9}, {%0,%1,%2,%3};"
        : "+f"(c[0]), "+f"(c[1]), "+f"(c[2]), "+f"(c[3])
        : "r"(a[0]), "r"(a[1]), "r"(a[2]), "r"(a[3]), "r"(b0), "r"(b1));
}
__device__ __forceinline__ void mma_f16(float* c, const uint32_t* a,
                                        uint32_t b0, uint32_t b1) {
    asm volatile(
        "mma.sync.aligned.m16n8k16.row.col.f32.f16.f16.f32 "
        "{%0,%1,%2,%3}, {%4,%5,%6,%7}, {%8,%9}, {%0,%1,%2,%3};"
        : "+f"(c[0]), "+f"(c[1]), "+f"(c[2]), "+f"(c[3])
        : "r"(a[0]), "r"(a[1]), "r"(a[2]), "r"(a[3]), "r"(b0), "r"(b1));
}
__device__ __forceinline__ void ldsm_x4(uint32_t* r, uint32_t addr) {
    asm volatile("ldmatrix.sync.aligned.m8n8.x4.shared.b16 {%0,%1,%2,%3}, [%4];"
                 : "=r"(r[0]), "=r"(r[1]), "=r"(r[2]), "=r"(r[3]) : "r"(addr));
}

// ---------------- layer GEMM (fp16 2-term, 512 thr, 4-way K-split, PDL) -----
// O = relu((Ah+Al) @ W^T + bias) (+ ext_next). CTA tile 32x64, KC=128.
// 16 warps (wm2 x wn2 x kslot4), warp tile 16x32, K quarter per warp;
// 4-way cross-warp reduction via SMEM. Stage 32KB {A hi 8K, A lo 8K, B 16K},
// 3 stages, prefetch distance 2, one __syncthreads per chunk.
// B stages 0,1 prefetched BEFORE griddepcontrol.wait (weights are static).
#define M_TILE 32
#define N_TILE 64
#define KC     128
#define NCHUNK (SS / KC)          // 8
#define STG    32768
#define SB_ALO 8192
#define SB_B   16384
#define SM_TOTAL (3 * STG)        // 98304
#define NTHR   512

// swizzled unit offset within a 256B row (16 units), conflict-free for ldsm
#define SWU(cu, row) ((((cu) & 8) | (((cu) & 7) ^ ((row) & 7))) << 4)

__device__ __forceinline__ void load_A(uint32_t st, int kc0, int tid, int m0,
    const __half* __restrict__ Ah, const __half* __restrict__ Al)
{
    #pragma unroll
    for (int i = 0; i < 2; i++) {
        int u = tid + (i << 9);          // 0..1023
        int sel = u >> 9;                // 0 hi, 1 lo
        int v = u & 511;
        int row = v >> 4, cu = v & 15;
        const __half* src = (sel ? Al : Ah) + (size_t)(m0 + row) * SS + kc0 + cu * 8;
        cp16(st + (sel ? SB_ALO : 0) + row * 256 + SWU(cu, row), src);
    }
}
__device__ __forceinline__ void load_B(uint32_t st, int kc0, int tid, int n0,
    const __half* __restrict__ W)
{
    #pragma unroll
    for (int i = 0; i < 2; i++) {
        int u = tid + (i << 9);          // 0..1023
        int row = u >> 4, cu = u & 15;   // 64 rows x 16 units
        const __half* src = W + (size_t)(n0 + row) * SS + kc0 + cu * 8;
        cp16(st + SB_B + row * 256 + SWU(cu, row), src);
    }
}

__global__ __launch_bounds__(NTHR) void layer_kernel(
    const __half* __restrict__ Ah, const __half* __restrict__ Al,
    const __half* __restrict__ W,
    const float* __restrict__ bias, const float* __restrict__ ext_next,
    __half* __restrict__ Oh, __half* __restrict__ Ol)
{
    extern __shared__ char smem[];
    const uint32_t sb = smem_u32(smem);
    const int tid = threadIdx.x;
    const int wid = tid >> 5, lane = tid & 31;
    const int g = lane >> 2, t4 = lane & 3;
    const int wm = (wid >> 3) & 1;       // rows wm*16
    const int wn = (wid >> 2) & 1;       // cols wn*32
    const int kslot = wid & 3;           // K quarter
    const int m0 = blockIdx.x * M_TILE, n0 = blockIdx.y * N_TILE;

    const int lr = lane & 7;
    const int half8 = (lane >> 3) & 1;
    const int khalf = (lane >> 4) & 1;
    const int rowA  = wm * 16 + half8 * 8 + lr;
    const int rowB0 = wn * 32 + half8 * 8 + lr;
    const int rowB1 = rowB0 + 16;

    // Prefetch weight stages 0,1 BEFORE the grid dependency (W is static).
    load_B(sb, 0, tid, n0, W);              cp_commit();   // g0 = B0
    load_B(sb + STG, KC, tid, n0, W);       cp_commit();   // g1 = B1
    gdc_wait();                                            // prev layer done
    load_A(sb, 0, tid, m0, Ah, Al);         cp_commit();   // g2 = A0
    load_A(sb + STG, KC, tid, m0, Ah, Al);  cp_commit();   // g3 = A1

    float acc[4][4] = {};
    int st_c = 0, st_p = 2;   // stage of chunk c, stage of chunk c+2

    #pragma unroll 1
    for (int c = 0; c < NCHUNK; c++) {
        if (c < NCHUNK - 1) cp_wait1(); else cp_wait0();
        __syncthreads();
        if (c + 2 < NCHUNK) {
            const uint32_t sp = sb + st_p * STG;
            load_A(sp, (c + 2) * KC, tid, m0, Ah, Al);
            load_B(sp, (c + 2) * KC, tid, n0, W);
            cp_commit();
        }

        const uint32_t aBase = sb + st_c * STG;
        const uint32_t bBase = aBase + SB_B;
        #pragma unroll
        for (int k2 = 0; k2 < 2; k2++) {
            const int u = (kslot * 2 + k2) * 2 + khalf;   // 0..15
            uint32_t ah[4], al[4], b0[4], b1[4];
            ldsm_x4(ah, aBase + rowA * 256 + SWU(u, rowA));
            ldsm_x4(al, aBase + SB_ALO + rowA * 256 + SWU(u, rowA));
            ldsm_x4(b0, bBase + rowB0 * 256 + SWU(u, rowB0));
            ldsm_x4(b1, bBase + rowB1 * 256 + SWU(u, rowB1));
            mma_f16(acc[0], ah, b0[0], b0[2]);
            mma_f16(acc[1], ah, b0[1], b0[3]);
            mma_f16(acc[2], ah, b1[0], b1[2]);
            mma_f16(acc[3], ah, b1[1], b1[3]);
            mma_f16(acc[0], al, b0[0], b0[2]);
            mma_f16(acc[1], al, b0[1], b0[3]);
            mma_f16(acc[2], al, b1[0], b1[2]);
            mma_f16(acc[3], al, b1[1], b1[3]);
        }
        st_c = (st_c == 2) ? 0 : st_c + 1;
        st_p = (st_p == 2) ? 0 : st_p + 1;
    }
    __syncthreads();   // all warps done with last stage before scratch overlay

    // 4-way cross-warp K reduction (scratch overlays the stages).
    float* scr = (float*)smem;
    const int group = wid >> 2;              // 0..3 = (wm,wn)
    if (kslot != 0) {
        float4* p = (float4*)scr + ((group * 3 + (kslot - 1)) * 32 + lane) * 4;
        #pragma unroll
        for (int jj = 0; jj < 4; jj++)
            p[jj] = make_float4(acc[jj][0], acc[jj][1], acc[jj][2], acc[jj][3]);
    }
    __syncthreads();
    if (kslot == 0) {
        #pragma unroll
        for (int d = 0; d < 3; d++) {
            const float4* p = (const float4*)scr + ((group * 3 + d) * 32 + lane) * 4;
            #pragma unroll
            for (int jj = 0; jj < 4; jj++) {
                float4 v = p[jj];
                acc[jj][0] += v.x; acc[jj][1] += v.y; acc[jj][2] += v.z; acc[jj][3] += v.w;
            }
        }
        const int row0 = m0 + wm * 16 + g;
        const int row1 = row0 + 8;
        #pragma unroll
        for (int jj = 0; jj < 4; jj++) {
            const int col = n0 + wn * 32 + jj * 8 + t4 * 2;
            float2 bb = *(const float2*)(bias + col);
            float v00 = fmaxf(acc[jj][0] + bb.x, 0.0f);
            float v01 = fmaxf(acc[jj][1] + bb.y, 0.0f);
            float v10 = fmaxf(acc[jj][2] + bb.x, 0.0f);
            float v11 = fmaxf(acc[jj][3] + bb.y, 0.0f);
            if (ext_next) {
                float2 e0 = *(const float2*)(ext_next + (size_t)row0 * SS + col);
                float2 e1 = *(const float2*)(ext_next + (size_t)row1 * SS + col);
                v00 += e0.x; v01 += e0.y; v10 += e1.x; v11 += e1.y;
            }
            __half h00 = __float2half_rn(v00), h01 = __float2half_rn(v01);
            __half h10 = __float2half_rn(v10), h11 = __float2half_rn(v11);
            __half l00 = __float2half_rn(v00 - __half2float(h00));
            __half l01 = __float2half_rn(v01 - __half2float(h01));
            __half l10 = __float2half_rn(v10 - __half2float(h10));
            __half l11 = __float2half_rn(v11 - __half2float(h11));
            *(uint32_t*)(Oh + (size_t)row0 * SS + col) =
                (uint32_t)__half_as_ushort(h00) | ((uint32_t)__half_as_ushort(h01) << 16);
            *(uint32_t*)(Oh + (size_t)row1 * SS + col) =
                (uint32_t)__half_as_ushort(h10) | ((uint32_t)__half_as_ushort(h11) << 16);
            *(uint32_t*)(Ol + (size_t)row0 * SS + col) =
                (uint32_t)__half_as_ushort(l00) | ((uint32_t)__half_as_ushort(l01) << 16);
            *(uint32_t*)(Ol + (size_t)row1 * SS + col) =
                (uint32_t)__half_as_ushort(l10) | ((uint32_t)__half_as_ushort(l11) << 16);
        }
    }
    gdc_launch();
}

// ---------------- input projection (bf16 3-term MMA; also writes s0) --------
#define PA_HI 0
#define PA_LO 16384
#define PB_HI 32768
#define PB_LO 49152
#define P_SM  65536

__global__ __launch_bounds__(256) void proj_mma(
    const __nv_bfloat16* __restrict__ Xh, const __nv_bfloat16* __restrict__ Xl,
    const __nv_bfloat16* __restrict__ Wh, const __nv_bfloat16* __restrict__ Wl,
    const float* __restrict__ bias, float* __restrict__ Out,
    __half* __restrict__ S0h, __half* __restrict__ S0l)
{
    extern __shared__ char smem[];
    const uint32_t sb = smem_u32(smem);
    const int tid = threadIdx.x;
    const int wid = tid >> 5, lane = tid & 31;
    const int g = lane >> 2, t4 = lane & 3;
    const int wm = (wid >> 1) << 4;
    const int wn = (wid & 1) << 5;
    const int m0 = blockIdx.x * 64, n0 = blockIdx.y * 64;

    #pragma unroll
    for (int i = 0; i < 16; i++) {
        int u = tid + (i << 8);
        const __nv_bfloat16* src;
        uint32_t dst;
        if (u < 2048) {
            int sel = u >> 10, v = u & 1023;
            int row = v >> 4, cu = v & 15;
            src = (sel ? Xl : Xh) + (size_t)(m0 + row) * IND + cu * 8;
            dst = sb + (sel ? PA_LO : PA_HI) + row * 256 + SWU(cu, row);
        } else {
            int w = u - 2048;
            int sel = w >> 10, v = w & 1023;
            int row = v >> 4, cu = v & 15;
            src = (sel ? Wl : Wh) + (size_t)(n0 + row) * IND + cu * 8;
            dst = sb + (sel ? PB_LO : PB_HI) + row * 256 + SWU(cu, row);
        }
        cp16(dst, src);
    }
    cp_commit();
    cp_wait0();
    __syncthreads();

    const int lr = lane & 7;
    const int half8 = (lane >> 3) & 1;
    const int khalf = (lane >> 4) & 1;
    const int rowA = wm + half8 * 8 + lr;
    const int rowB = wn + half8 * 8 + lr;

    float acc[4][4] = {};
    #pragma unroll
    for (int ks = 0; ks < 8; ks++) {
        const int u = ks * 2 + khalf;
        uint32_t ah[4], al[4];
        ldsm_x4(ah, sb + PA_HI + rowA * 256 + SWU(u, rowA));
        ldsm_x4(al, sb + PA_LO + rowA * 256 + SWU(u, rowA));
        #pragma unroll
        for (int jj = 0; jj < 2; jj++) {
            uint32_t bh[4], bl[4];
            ldsm_x4(bh, sb + PB_HI + (rowB + jj * 16) * 256 + SWU(u, rowB + jj * 16));
            ldsm_x4(bl, sb + PB_LO + (rowB + jj * 16) * 256 + SWU(u, rowB + jj * 16));
            mma_bf16(acc[jj * 2],     ah, bh[0], bh[2]);
            mma_bf16(acc[jj * 2],     ah, bl[0], bl[2]);
            mma_bf16(acc[jj * 2],     al, bh[0], bh[2]);
            mma_bf16(acc[jj * 2 + 1], ah, bh[1], bh[3]);
            mma_bf16(acc[jj * 2 + 1], ah, bl[1], bl[3]);
            mma_bf16(acc[jj * 2 + 1], al, bh[1], bh[3]);
        }
    }

    const int r0 = m0 + wm + g;
    const int r1 = r0 + 8;
    const int b0r = r0 >> 8, t0r = r0 & 255;
    const int b1r = r1 >> 8, t1r = r1 & 255;
    #pragma unroll
    for (int j = 0; j < 4; j++) {
        const int col = n0 + wn + j * 8 + t4 * 2;
        float2 bb = *(const float2*)(bias + col);
        float2 o0 = make_float2(acc[j][0] + bb.x, acc[j][1] + bb.y);
        float2 o1 = make_float2(acc[j][2] + bb.x, acc[j][3] + bb.y);
        *(float2*)(Out + ((size_t)t0r * BB + b0r) * SS + col) = o0;
        *(float2*)(Out + ((size_t)t1r * BB + b1r) * SS + col) = o1;
        if (t0r == 0) {       // s0 = ext[0] in fp16 hi/lo
            __half h0 = __float2half_rn(o0.x), h1 = __float2half_rn(o0.y);
            __half l0 = __float2half_rn(o0.x - __half2float(h0));
            __half l1 = __float2half_rn(o0.y - __half2float(h1));
            *(uint32_t*)(S0h + (size_t)b0r * SS + col) =
                (uint32_t)__half_as_ushort(h0) | ((uint32_t)__half_as_ushort(h1) << 16);
            *(uint32_t*)(S0l + (size_t)b0r * SS + col) =
                (uint32_t)__half_as_ushort(l0) | ((uint32_t)__half_as_ushort(l1) << 16);
        }
    }
}

// ---------------- fused prolog: all conversions in ONE launch ----------------
#define N_W   (SS * SS / 4)
#define N_X   ((size_t)BB * TT * IND / 4)
#define N_WIN (SS * IND / 4)
#define N_TOT (2 * N_W + (int)N_X + N_WIN)

__global__ void prep_kernel(
    const float4* __restrict__ Wr1, const float4* __restrict__ Wr2,
    const float4* __restrict__ X,   const float4* __restrict__ Win,
    uint2* __restrict__ W1, uint2* __restrict__ W2,
    uint2* __restrict__ xh, uint2* __restrict__ xl,
    uint2* __restrict__ wih, uint2* __restrict__ wil)
{
    int i = blockIdx.x * blockDim.x + threadIdx.x;
    if (i >= N_TOT) return;
    if (i < 2 * N_W) {
        const float4* src = (i < N_W) ? Wr1 : Wr2;
        uint2* dst        = (i < N_W) ? W1  : W2;
        int k = (i < N_W) ? i : i - N_W;
        float4 v = src[k];
        uint2 O;
        O.x = (uint32_t)__half_as_ushort(__float2half_rn(v.x))
            | ((uint32_t)__half_as_ushort(__float2half_rn(v.y)) << 16);
        O.y = (uint32_t)__half_as_ushort(__float2half_rn(v.z))
            | ((uint32_t)__half_as_ushort(__float2half_rn(v.w)) << 16);
        dst[k] = O;
    } else {
        int k = i - 2 * N_W;
        const float4* src; uint2 *dh, *dl;
        if (k < (int)N_X) { src = X; dh = xh; dl = xl; }
        else { k -= (int)N_X; src = Win; dh = wih; dl = wil; }
        float4 v = src[k];
        __nv_bfloat16 h0 = __float2bfloat16(v.x), h1 = __float2bfloat16(v.y);
        __nv_bfloat16 h2 = __float2bfloat16(v.z), h3 = __float2bfloat16(v.w);
        __nv_bfloat16 l0 = __float2bfloat16(v.x - __bfloat162float(h0));
        __nv_bfloat16 l1 = __float2bfloat16(v.y - __bfloat162float(h1));
        __nv_bfloat16 l2 = __float2bfloat16(v.z - __bfloat162float(h2));
        __nv_bfloat16 l3 = __float2bfloat16(v.w - __bfloat162float(h3));
        uint2 H, L;
        H.x = (uint32_t)__bfloat16_as_ushort(h0) | ((uint32_t)__bfloat16_as_ushort(h1) << 16);
        H.y = (uint32_t)__bfloat16_as_ushort(h2) | ((uint32_t)__bfloat16_as_ushort(h3) << 16);
        L.x = (uint32_t)__bfloat16_as_ushort(l0) | ((uint32_t)__bfloat16_as_ushort(l1) << 16);
        L.y = (uint32_t)__bfloat16_as_ushort(l2) | ((uint32_t)__bfloat16_as_ushort(l3) << 16);
        dh[k] = H; dl[k] = L;
    }
}

// ---------------- broadcast final state (fp16 hi+lo -> fp32) ----------------
__global__ void bcastH_kernel(const uint2* __restrict__ hi, const uint2* __restrict__ lo,
                              float4* __restrict__ out)
{
    int i = blockIdx.x * blockDim.x + threadIdx.x;
    int b  = i >> 16;
    int s4 = i & 255;
    uint2 H = hi[(b << 8) + s4];
    uint2 L = lo[(b << 8) + s4];
    float4 o;
    o.x = __half2float(__ushort_as_half((unsigned short)(H.x & 0xFFFF)))
        + __half2float(__ushort_as_half((unsigned short)(L.x & 0xFFFF)));
    o.y = __half2float(__ushort_as_half((unsigned short)(H.x >> 16)))
        + __half2float(__ushort_as_half((unsigned short)(L.x >> 16)));
    o.z = __half2float(__ushort_as_half((unsigned short)(H.y & 0xFFFF)))
        + __half2float(__ushort_as_half((unsigned short)(L.y & 0xFFFF)));
    o.w = __half2float(__ushort_as_half((unsigned short)(H.y >> 16)))
        + __half2float(__ushort_as_half((unsigned short)(L.y >> 16)));
    out[i] = o;
}

// ---------------- driver ----------------------------------------------------
extern "C" void kernel_launch(void* const* d_in, const int* in_sizes, int n_in,
                              void* d_out, int out_size)
{
    const float* x      = (const float*)d_in[0];
    const float* W_in   = (const float*)d_in[1];
    const float* b_in   = (const float*)d_in[2];
    const float* W_rec  = (const float*)d_in[3];
    const float* b_rec  = (const float*)d_in[4];
    const float* W_rec2 = (const float*)d_in[5];
    const float* b_rec2 = (const float*)d_in[6];
    float* out = (float*)d_out;

    float* ext;
    __half *sAh, *sAl, *sBh, *sBl, *W1, *W2;
    __nv_bfloat16 *xh, *xl, *Winh, *Winl;
    cudaGetSymbolAddress((void**)&ext, g_ext);
    cudaGetSymbolAddress((void**)&sAh, g_sAh);
    cudaGetSymbolAddress((void**)&sAl, g_sAl);
    cudaGetSymbolAddress((void**)&sBh, g_sBh);
    cudaGetSymbolAddress((void**)&sBl, g_sBl);
    cudaGetSymbolAddress((void**)&W1,  g_W1);
    cudaGetSymbolAddress((void**)&W2,  g_W2);
    cudaGetSymbolAddress((void**)&xh,  g_xh);
    cudaGetSymbolAddress((void**)&xl,  g_xl);
    cudaGetSymbolAddress((void**)&Winh, g_Winh);
    cudaGetSymbolAddress((void**)&Winl, g_Winl);

    cudaFuncSetAttribute(layer_kernel, cudaFuncAttributeMaxDynamicSharedMemorySize, SM_TOTAL);
    cudaFuncSetAttribute(proj_mma,     cudaFuncAttributeMaxDynamicSharedMemorySize, P_SM);

    // Launch 0: fused prolog
    prep_kernel<<<(N_TOT + 255) / 256, 256>>>(
        (const float4*)W_rec, (const float4*)W_rec2,
        (const float4*)x, (const float4*)W_in,
        (uint2*)W1, (uint2*)W2, (uint2*)xh, (uint2*)xl, (uint2*)Winh, (uint2*)Winl);

    // Launch 1: ext = x @ W_in^T + b_in; also writes s0 = ext[0] hi/lo
    {
        dim3 grid((BB * TT) / 64, SS / 64);
        proj_mma<<<grid, 256, P_SM>>>(xh, xl, Winh, Winl, b_in, ext, sAh, sAl);
    }

    // Launches 2..513: scan, PDL-chained
    {
        cudaLaunchConfig_t cfg = {};
        cfg.gridDim  = dim3(BB / M_TILE, SS / N_TILE, 1);   // (8, 16) = 128 CTAs
        cfg.blockDim = dim3(NTHR, 1, 1);
        cfg.dynamicSmemBytes = SM_TOTAL;
        cudaLaunchAttribute at[1];
        at[0].id = cudaLaunchAttributeProgrammaticStreamSerialization;
        at[0].val.programmaticStreamSerializationAllowed = 1;
        cfg.attrs = at;
        cfg.numAttrs = 1;

        const float* nil = nullptr;
        for (int t = 0; t < TT; t++) {
            if (cudaLaunchKernelEx(&cfg, layer_kernel,
                    (const __half*)sAh, (const __half*)sAl, (const __half*)W1,
                    (const float*)b_rec, nil, sBh, sBl) != cudaSuccess)
                layer_kernel<<<cfg.gridDim, cfg.blockDim, SM_TOTAL>>>(
                    sAh, sAl, W1, b_rec, nullptr, sBh, sBl);
            const float* en = (t + 1 < TT) ? ext + (size_t)(t + 1) * BB * SS : nullptr;
            if (cudaLaunchKernelEx(&cfg, layer_kernel,
                    (const __half*)sBh, (const __half*)sBl, (const __half*)W2,
                    (const float*)b_rec2, en, sAh, sAl) != cudaSuccess)
                layer_kernel<<<cfg.gridDim, cfg.blockDim, SM_TOTAL>>>(
                    sBh, sBl, W2, b_rec2, en, sAh, sAl);
        }
    }

    // Final: broadcast final state
    bcastH_kernel<<<(BB * TT * SS / 4) / 256, 256>>>((const uint2*)sAh, (const uint2*)sAl, (float4*)out);
}

// round 10
// speedup vs baseline: 2.5242x; 1.3202x over previous
#include <cuda_runtime.h>
#include <cuda_bf16.h>
#include <cuda_fp16.h>
#include <cstdint>

// Problem dims
#define BB  256
#define TT  256
#define IND 128
#define SS  1024

// ---------------- scratch (__device__ globals) ------------------------------
__device__ float g_ext[(size_t)TT * BB * SS];            // [t][b][s] fp32
__device__ __half g_sA[BB * SS];                         // state fp16 (ping)
__device__ __half g_sB[BB * SS];                         // state fp16 (pong)
__device__ __half g_W1[SS * SS], g_W2[SS * SS];          // weights fp16
__device__ __nv_bfloat16 g_xh[(size_t)BB * TT * IND], g_xl[(size_t)BB * TT * IND];
__device__ __nv_bfloat16 g_Winh[SS * IND], g_Winl[SS * IND];

// ---------------- helpers ---------------------------------------------------
__device__ __forceinline__ uint32_t smem_u32(const void* p) {
    uint32_t a;
    asm("{ .reg .u64 t; cvta.to.shared.u64 t, %1; cvt.u32.u64 %0, t; }" : "=r"(a) : "l"(p));
    return a;
}
__device__ __forceinline__ void cp16(uint32_t dst, const void* src) {
    asm volatile("cp.async.cg.shared.global [%0], [%1], 16;" :: "r"(dst), "l"(src));
}
__device__ __forceinline__ void cp_commit() { asm volatile("cp.async.commit_group;"); }
__device__ __forceinline__ void cp_wait0()  { asm volatile("cp.async.wait_group 0;"); }
__device__ __forceinline__ void cp_wait1()  { asm volatile("cp.async.wait_group 1;"); }
__device__ __forceinline__ void gdc_wait()   { asm volatile("griddepcontrol.wait;" ::: "memory"); }
__device__ __forceinline__ void gdc_launch() { asm volatile("griddepcontrol.launch_dependents;"); }

__device__ __forceinline__ void mma_bf16(float* c, const uint32_t* a,
                                         uint32_t b0, uint32_t b1) {
    asm volatile(
        "mma.sync.aligned.m16n8k16.row.col.f32.bf16.bf16.f32 "
        "{%0,%1,%2,%3}, {%4,%5,%6,%7}, {%8,%9}, {%0,%1,%2,%3};"
        : "+f"(c[0]), "+f"(c[1]), "+f"(c[2]), "+f"(c[3])
        : "r"(a[0]), "r"(a[1]), "r"(a[2]), "r"(a[3]), "r"(b0), "r"(b1));
}
__device__ __forceinline__ void mma_f16(float* c, const uint32_t* a,
                                        uint32_t b0, uint32_t b1) {
    asm volatile(
        "mma.sync.aligned.m16n8k16.row.col.f32.f16.f16.f32 "
        "{%0,%1,%2,%3}, {%4,%5,%6,%7}, {%8,%9}, {%0,%1,%2,%3};"
        : "+f"(c[0]), "+f"(c[1]), "+f"(c[2]), "+f"(c[3])
        : "r"(a[0]), "r"(a[1]), "r"(a[2]), "r"(a[3]), "r"(b0), "r"(b1));
}
__device__ __forceinline__ void ldsm_x4(uint32_t* r, uint32_t addr) {
    asm volatile("ldmatrix.sync.aligned.m8n8.x4.shared.b16 {%0,%1,%2,%3}, [%4];"
                 : "=r"(r[0]), "=r"(r[1]), "=r"(r[2]), "=r"(r[3]) : "r"(addr));
}

// ---------------- layer GEMM (fp16 1-term, 512 thr, 4-way K-split, PDL) -----
// O = relu(A @ W^T + bias) (+ ext_next). A is plain fp16 state.
// CTA tile 32x64, KC=256, NCHUNK=4. 16 warps (wm2 x wn2 x kslot4),
// warp tile 16x32, K quarter per warp; 4-way cross-warp reduction via SMEM.
// Stage 48KB {A 16K, B 32K}, 3 stages, prefetch distance 2, 1 sync/chunk.
// B stages 0,1 prefetched BEFORE griddepcontrol.wait (weights are static).
#define M_TILE 32
#define N_TILE 64
#define KC     256
#define NCHUNK (SS / KC)          // 4
#define STG    49152
#define SB_B   16384
#define SM_TOTAL (3 * STG)        // 147456
#define NTHR   512

// swizzled 16B-unit offset within a 512B row (32 units), ldsm conflict-free
#define SWU(cu, row) ((((cu) & 24) | (((cu) & 7) ^ ((row) & 7))) << 4)

__device__ __forceinline__ void load_A(uint32_t st, int kc0, int tid, int m0,
    const __half* __restrict__ A)
{
    #pragma unroll
    for (int i = 0; i < 2; i++) {
        int u = tid + (i << 9);          // 0..1023 = 32 rows x 32 units
        int row = u >> 5, cu = u & 31;
        const __half* src = A + (size_t)(m0 + row) * SS + kc0 + cu * 8;
        cp16(st + row * 512 + SWU(cu, row), src);
    }
}
__device__ __forceinline__ void load_B(uint32_t st, int kc0, int tid, int n0,
    const __half* __restrict__ W)
{
    #pragma unroll
    for (int i = 0; i < 4; i++) {
        int u = tid + (i << 9);          // 0..2047 = 64 rows x 32 units
        int row = u >> 5, cu = u & 31;
        const __half* src = W + (size_t)(n0 + row) * SS + kc0 + cu * 8;
        cp16(st + SB_B + row * 512 + SWU(cu, row), src);
    }
}

__global__ __launch_bounds__(NTHR) void layer_kernel(
    const __half* __restrict__ A, const __half* __restrict__ W,
    const float* __restrict__ bias, const float* __restrict__ ext_next,
    __half* __restrict__ O)
{
    extern __shared__ char smem[];
    const uint32_t sb = smem_u32(smem);
    const int tid = threadIdx.x;
    const int wid = tid >> 5, lane = tid & 31;
    const int g = lane >> 2, t4 = lane & 3;
    const int wm = (wid >> 3) & 1;       // rows wm*16
    const int wn = (wid >> 2) & 1;       // cols wn*32
    const int kslot = wid & 3;           // K quarter (64 k per chunk)
    const int m0 = blockIdx.x * M_TILE, n0 = blockIdx.y * N_TILE;

    const int lr = lane & 7;
    const int half8 = (lane >> 3) & 1;
    const int khalf = (lane >> 4) & 1;
    const int rowA  = wm * 16 + half8 * 8 + lr;
    const int rowB0 = wn * 32 + half8 * 8 + lr;
    const int rowB1 = rowB0 + 16;

    // Prefetch weight stages 0,1 BEFORE the grid dependency (W is static).
    load_B(sb, 0, tid, n0, W);              cp_commit();   // g0 = B0
    load_B(sb + STG, KC, tid, n0, W);       cp_commit();   // g1 = B1
    gdc_wait();                                            // prev layer done
    load_A(sb, 0, tid, m0, A);              cp_commit();   // g2 = A0
    load_A(sb + STG, KC, tid, m0, A);       cp_commit();   // g3 = A1

    float acc[4][4] = {};
    int st_c = 0, st_p = 2;   // stage of chunk c, stage of chunk c+2

    #pragma unroll 1
    for (int c = 0; c < NCHUNK; c++) {
        if (c < NCHUNK - 1) cp_wait1(); else cp_wait0();
        __syncthreads();
        if (c + 2 < NCHUNK) {
            const uint32_t sp = sb + st_p * STG;
            load_A(sp, (c + 2) * KC, tid, m0, A);
            load_B(sp, (c + 2) * KC, tid, n0, W);
            cp_commit();
        }

        const uint32_t aBase = sb + st_c * STG;
        const uint32_t bBase = aBase + SB_B;
        #pragma unroll
        for (int k2 = 0; k2 < 4; k2++) {
            const int u = (kslot * 4 + k2) * 2 + khalf;   // 0..31
            uint32_t ah[4], b0[4], b1[4];
            ldsm_x4(ah, aBase + rowA * 512 + SWU(u, rowA));
            ldsm_x4(b0, bBase + rowB0 * 512 + SWU(u, rowB0));
            ldsm_x4(b1, bBase + rowB1 * 512 + SWU(u, rowB1));
            mma_f16(acc[0], ah, b0[0], b0[2]);
            mma_f16(acc[1], ah, b0[1], b0[3]);
            mma_f16(acc[2], ah, b1[0], b1[2]);
            mma_f16(acc[3], ah, b1[1], b1[3]);
        }
        st_c = (st_c == 2) ? 0 : st_c + 1;
        st_p = (st_p == 2) ? 0 : st_p + 1;
    }
    __syncthreads();   // all warps done with last stage before scratch overlay

    // 4-way cross-warp K reduction (scratch overlays the stages).
    float* scr = (float*)smem;
    const int group = wid >> 2;              // 0..3 = (wm,wn)
    if (kslot != 0) {
        float4* p = (float4*)scr + ((group * 3 + (kslot - 1)) * 32 + lane) * 4;
        #pragma unroll
        for (int jj = 0; jj < 4; jj++)
            p[jj] = make_float4(acc[jj][0], acc[jj][1], acc[jj][2], acc[jj][3]);
    }
    __syncthreads();
    if (kslot == 0) {
        #pragma unroll
        for (int d = 0; d < 3; d++) {
            const float4* p = (const float4*)scr + ((group * 3 + d) * 32 + lane) * 4;
            #pragma unroll
            for (int jj = 0; jj < 4; jj++) {
                float4 v = p[jj];
                acc[jj][0] += v.x; acc[jj][1] += v.y; acc[jj][2] += v.z; acc[jj][3] += v.w;
            }
        }
        const int row0 = m0 + wm * 16 + g;
        const int row1 = row0 + 8;
        #pragma unroll
        for (int jj = 0; jj < 4; jj++) {
            const int col = n0 + wn * 32 + jj * 8 + t4 * 2;
            float2 bb = *(const float2*)(bias + col);
            float v00 = fmaxf(acc[jj][0] + bb.x, 0.0f);
            float v01 = fmaxf(acc[jj][1] + bb.y, 0.0f);
            float v10 = fmaxf(acc[jj][2] + bb.x, 0.0f);
            float v11 = fmaxf(acc[jj][3] + bb.y, 0.0f);
            if (ext_next) {
                float2 e0 = *(const float2*)(ext_next + (size_t)row0 * SS + col);
                float2 e1 = *(const float2*)(ext_next + (size_t)row1 * SS + col);
                v00 += e0.x; v01 += e0.y; v10 += e1.x; v11 += e1.y;
            }
            *(uint32_t*)(O + (size_t)row0 * SS + col) =
                (uint32_t)__half_as_ushort(__float2half_rn(v00))
                | ((uint32_t)__half_as_ushort(__float2half_rn(v01)) << 16);
            *(uint32_t*)(O + (size_t)row1 * SS + col) =
                (uint32_t)__half_as_ushort(__float2half_rn(v10))
                | ((uint32_t)__half_as_ushort(__float2half_rn(v11)) << 16);
        }
    }
    gdc_launch();
}

// ---------------- input projection (bf16 3-term MMA; also writes s0) --------
#define PA_HI 0
#define PA_LO 16384
#define PB_HI 32768
#define PB_LO 49152
#define P_SM  65536

// 16-unit-row swizzle used by proj (256B rows)
#define SWU16(cu, row) ((((cu) & 8) | (((cu) & 7) ^ ((row) & 7))) << 4)

__global__ __launch_bounds__(256) void proj_mma(
    const __nv_bfloat16* __restrict__ Xh, const __nv_bfloat16* __restrict__ Xl,
    const __nv_bfloat16* __restrict__ Wh, const __nv_bfloat16* __restrict__ Wl,
    const float* __restrict__ bias, float* __restrict__ Out,
    __half* __restrict__ S0)
{
    extern __shared__ char smem[];
    const uint32_t sb = smem_u32(smem);
    const int tid = threadIdx.x;
    const int wid = tid >> 5, lane = tid & 31;
    const int g = lane >> 2, t4 = lane & 3;
    const int wm = (wid >> 1) << 4;
    const int wn = (wid & 1) << 5;
    const int m0 = blockIdx.x * 64, n0 = blockIdx.y * 64;

    #pragma unroll
    for (int i = 0; i < 16; i++) {
        int u = tid + (i << 8);
        const __nv_bfloat16* src;
        uint32_t dst;
        if (u < 2048) {
            int sel = u >> 10, v = u & 1023;
            int row = v >> 4, cu = v & 15;
            src = (sel ? Xl : Xh) + (size_t)(m0 + row) * IND + cu * 8;
            dst = sb + (sel ? PA_LO : PA_HI) + row * 256 + SWU16(cu, row);
        } else {
            int w = u - 2048;
            int sel = w >> 10, v = w & 1023;
            int row = v >> 4, cu = v & 15;
            src = (sel ? Wl : Wh) + (size_t)(n0 + row) * IND + cu * 8;
            dst = sb + (sel ? PB_LO : PB_HI) + row * 256 + SWU16(cu, row);
        }
        cp16(dst, src);
    }
    cp_commit();
    cp_wait0();
    __syncthreads();

    const int lr = lane & 7;
    const int half8 = (lane >> 3) & 1;
    const int khalf = (lane >> 4) & 1;
    const int rowA = wm + half8 * 8 + lr;
    const int rowB = wn + half8 * 8 + lr;

    float acc[4][4] = {};
    #pragma unroll
    for (int ks = 0; ks < 8; ks++) {
        const int u = ks * 2 + khalf;
        uint32_t ah[4], al[4];
        ldsm_x4(ah, sb + PA_HI + rowA * 256 + SWU16(u, rowA));
        ldsm_x4(al, sb + PA_LO + rowA * 256 + SWU16(u, rowA));
        #pragma unroll
        for (int jj = 0; jj < 2; jj++) {
            uint32_t bh[4], bl[4];
            ldsm_x4(bh, sb + PB_HI + (rowB + jj * 16) * 256 + SWU16(u, rowB + jj * 16));
            ldsm_x4(bl, sb + PB_LO + (rowB + jj * 16) * 256 + SWU16(u, rowB + jj * 16));
            mma_bf16(acc[jj * 2],     ah, bh[0], bh[2]);
            mma_bf16(acc[jj * 2],     ah, bl[0], bl[2]);
            mma_bf16(acc[jj * 2],     al, bh[0], bh[2]);
            mma_bf16(acc[jj * 2 + 1], ah, bh[1], bh[3]);
            mma_bf16(acc[jj * 2 + 1], ah, bl[1], bl[3]);
            mma_bf16(acc[jj * 2 + 1], al, bh[1], bh[3]);
        }
    }

    const int r0 = m0 + wm + g;
    const int r1 = r0 + 8;
    const int b0r = r0 >> 8, t0r = r0 & 255;
    const int b1r = r1 >> 8, t1r = r1 & 255;
    #pragma unroll
    for (int j = 0; j < 4; j++) {
        const int col = n0 + wn + j * 8 + t4 * 2;
        float2 bb = *(const float2*)(bias + col);
        float2 o0 = make_float2(acc[j][0] + bb.x, acc[j][1] + bb.y);
        float2 o1 = make_float2(acc[j][2] + bb.x, acc[j][3] + bb.y);
        *(float2*)(Out + ((size_t)t0r * BB + b0r) * SS + col) = o0;
        *(float2*)(Out + ((size_t)t1r * BB + b1r) * SS + col) = o1;
        if (t0r == 0) {       // s0 = ext[0] in fp16
            *(uint32_t*)(S0 + (size_t)b0r * SS + col) =
                (uint32_t)__half_as_ushort(__float2half_rn(o0.x))
                | ((uint32_t)__half_as_ushort(__float2half_rn(o0.y)) << 16);
        }
    }
}

// ---------------- fused prolog: all conversions in ONE launch ----------------
#define N_W   (SS * SS / 4)
#define N_X   ((size_t)BB * TT * IND / 4)
#define N_WIN (SS * IND / 4)
#define N_TOT (2 * N_W + (int)N_X + N_WIN)

__global__ void prep_kernel(
    const float4* __restrict__ Wr1, const float4* __restrict__ Wr2,
    const float4* __restrict__ X,   const float4* __restrict__ Win,
    uint2* __restrict__ W1, uint2* __restrict__ W2,
    uint2* __restrict__ xh, uint2* __restrict__ xl,
    uint2* __restrict__ wih, uint2* __restrict__ wil)
{
    int i = blockIdx.x * blockDim.x + threadIdx.x;
    if (i >= N_TOT) return;
    if (i < 2 * N_W) {
        const float4* src = (i < N_W) ? Wr1 : Wr2;
        uint2* dst        = (i < N_W) ? W1  : W2;
        int k = (i < N_W) ? i : i - N_W;
        float4 v = src[k];
        uint2 O;
        O.x = (uint32_t)__half_as_ushort(__float2half_rn(v.x))
            | ((uint32_t)__half_as_ushort(__float2half_rn(v.y)) << 16);
        O.y = (uint32_t)__half_as_ushort(__float2half_rn(v.z))
            | ((uint32_t)__half_as_ushort(__float2half_rn(v.w)) << 16);
        dst[k] = O;
    } else {
        int k = i - 2 * N_W;
        const float4* src; uint2 *dh, *dl;
        if (k < (int)N_X) { src = X; dh = xh; dl = xl; }
        else { k -= (int)N_X; src = Win; dh = wih; dl = wil; }
        float4 v = src[k];
        __nv_bfloat16 h0 = __float2bfloat16(v.x), h1 = __float2bfloat16(v.y);
        __nv_bfloat16 h2 = __float2bfloat16(v.z), h3 = __float2bfloat16(v.w);
        __nv_bfloat16 l0 = __float2bfloat16(v.x - __bfloat162float(h0));
        __nv_bfloat16 l1 = __float2bfloat16(v.y - __bfloat162float(h1));
        __nv_bfloat16 l2 = __float2bfloat16(v.z - __bfloat162float(h2));
        __nv_bfloat16 l3 = __float2bfloat16(v.w - __bfloat162float(h3));
        uint2 H, L;
        H.x = (uint32_t)__bfloat16_as_ushort(h0) | ((uint32_t)__bfloat16_as_ushort(h1) << 16);
        H.y = (uint32_t)__bfloat16_as_ushort(h2) | ((uint32_t)__bfloat16_as_ushort(h3) << 16);
        L.x = (uint32_t)__bfloat16_as_ushort(l0) | ((uint32_t)__bfloat16_as_ushort(l1) << 16);
        L.y = (uint32_t)__bfloat16_as_ushort(l2) | ((uint32_t)__bfloat16_as_ushort(l3) << 16);
        dh[k] = H; dl[k] = L;
    }
}

// ---------------- broadcast final state (fp16 -> fp32, all timesteps) -------
__global__ void bcastH_kernel(const uint2* __restrict__ s, float4* __restrict__ out)
{
    int i = blockIdx.x * blockDim.x + threadIdx.x;
    int b  = i >> 16;
    int s4 = i & 255;
    uint2 H = s[(b << 8) + s4];
    float4 o;
    o.x = __half2float(__ushort_as_half((unsigned short)(H.x & 0xFFFF)));
    o.y = __half2float(__ushort_as_half((unsigned short)(H.x >> 16)));
    o.z = __half2float(__ushort_as_half((unsigned short)(H.y & 0xFFFF)));
    o.w = __half2float(__ushort_as_half((unsigned short)(H.y >> 16)));
    out[i] = o;
}

// ---------------- driver ----------------------------------------------------
extern "C" void kernel_launch(void* const* d_in, const int* in_sizes, int n_in,
                              void* d_out, int out_size)
{
    const float* x      = (const float*)d_in[0];
    const float* W_in   = (const float*)d_in[1];
    const float* b_in   = (const float*)d_in[2];
    const float* W_rec  = (const float*)d_in[3];
    const float* b_rec  = (const float*)d_in[4];
    const float* W_rec2 = (const float*)d_in[5];
    const float* b_rec2 = (const float*)d_in[6];
    float* out = (float*)d_out;

    float* ext;
    __half *sA, *sB, *W1, *W2;
    __nv_bfloat16 *xh, *xl, *Winh, *Winl;
    cudaGetSymbolAddress((void**)&ext, g_ext);
    cudaGetSymbolAddress((void**)&sA,  g_sA);
    cudaGetSymbolAddress((void**)&sB,  g_sB);
    cudaGetSymbolAddress((void**)&W1,  g_W1);
    cudaGetSymbolAddress((void**)&W2,  g_W2);
    cudaGetSymbolAddress((void**)&xh,  g_xh);
    cudaGetSymbolAddress((void**)&xl,  g_xl);
    cudaGetSymbolAddress((void**)&Winh, g_Winh);
    cudaGetSymbolAddress((void**)&Winl, g_Winl);

    cudaFuncSetAttribute(layer_kernel, cudaFuncAttributeMaxDynamicSharedMemorySize, SM_TOTAL);
    cudaFuncSetAttribute(proj_mma,     cudaFuncAttributeMaxDynamicSharedMemorySize, P_SM);

    // Launch 0: fused prolog
    prep_kernel<<<(N_TOT + 255) / 256, 256>>>(
        (const float4*)W_rec, (const float4*)W_rec2,
        (const float4*)x, (const float4*)W_in,
        (uint2*)W1, (uint2*)W2, (uint2*)xh, (uint2*)xl, (uint2*)Winh, (uint2*)Winl);

    // Launch 1: ext = x @ W_in^T + b_in; also writes s0 = ext[0] fp16
    {
        dim3 grid((BB * TT) / 64, SS / 64);
        proj_mma<<<grid, 256, P_SM>>>(xh, xl, Winh, Winl, b_in, ext, sA);
    }

    // Launches 2..513: scan, PDL-chained
    {
        cudaLaunchConfig_t cfg = {};
        cfg.gridDim  = dim3(BB / M_TILE, SS / N_TILE, 1);   // (8, 16) = 128 CTAs
        cfg.blockDim = dim3(NTHR, 1, 1);
        cfg.dynamicSmemBytes = SM_TOTAL;
        cudaLaunchAttribute at[1];
        at[0].id = cudaLaunchAttributeProgrammaticStreamSerialization;
        at[0].val.programmaticStreamSerializationAllowed = 1;
        cfg.attrs = at;
        cfg.numAttrs = 1;

        const float* nil = nullptr;
        for (int t = 0; t < TT; t++) {
            if (cudaLaunchKernelEx(&cfg, layer_kernel,
                    (const __half*)sA, (const __half*)W1,
                    (const float*)b_rec, nil, sB) != cudaSuccess)
                layer_kernel<<<cfg.gridDim, cfg.blockDim, SM_TOTAL>>>(
                    sA, W1, b_rec, nullptr, sB);
            const float* en = (t + 1 < TT) ? ext + (size_t)(t + 1) * BB * SS : nullptr;
            if (cudaLaunchKernelEx(&cfg, layer_kernel,
                    (const __half*)sB, (const __half*)W2,
                    (const float*)b_rec2, en, sA) != cudaSuccess)
                layer_kernel<<<cfg.gridDim, cfg.blockDim, SM_TOTAL>>>(
                    sB, W2, b_rec2, en, sA);
        }
    }

    // Final: broadcast final state
    bcastH_kernel<<<(BB * TT * SS / 4) / 256, 256>>>((const uint2*)sA, (float4*)out);
}

// round 11
// speedup vs baseline: 2.8630x; 1.1342x over previous
#include <cuda_runtime.h>
#include <cuda_bf16.h>
#include <cuda_fp16.h>
#include <cstdint>

// Problem dims
#define BB  256
#define TT  256
#define IND 128
#define SS  1024

// ---------------- scratch (__device__ globals) ------------------------------
__device__ float g_ext[(size_t)TT * BB * SS];            // [t][b][s] fp32
__device__ __half g_sA[BB * SS];                         // state fp16 (ping)
__device__ __half g_sB[BB * SS];                         // state fp16 (pong)
__device__ __half g_W1[SS * SS], g_W2[SS * SS];          // weights fp16
__device__ __nv_bfloat16 g_xh[(size_t)BB * TT * IND], g_xl[(size_t)BB * TT * IND];
__device__ __nv_bfloat16 g_Winh[SS * IND], g_Winl[SS * IND];

// ---------------- helpers ---------------------------------------------------
__device__ __forceinline__ uint32_t smem_u32(const void* p) {
    uint32_t a;
    asm("{ .reg .u64 t; cvta.to.shared.u64 t, %1; cvt.u32.u64 %0, t; }" : "=r"(a) : "l"(p));
    return a;
}
__device__ __forceinline__ void cp16(uint32_t dst, const void* src) {
    asm volatile("cp.async.cg.shared.global [%0], [%1], 16;" :: "r"(dst), "l"(src));
}
__device__ __forceinline__ void cp_commit() { asm volatile("cp.async.commit_group;"); }
__device__ __forceinline__ void cp_wait0()  { asm volatile("cp.async.wait_group 0;"); }
__device__ __forceinline__ void cp_wait1()  { asm volatile("cp.async.wait_group 1;"); }
__device__ __forceinline__ void gdc_wait()   { asm volatile("griddepcontrol.wait;" ::: "memory"); }
__device__ __forceinline__ void gdc_launch() { asm volatile("griddepcontrol.launch_dependents;"); }
__device__ __forceinline__ void bar_named(int id) {
    asm volatile("bar.sync %0, 128;" :: "r"(id) : "memory");
}

__device__ __forceinline__ void mma_bf16(float* c, const uint32_t* a,
                                         uint32_t b0, uint32_t b1) {
    asm volatile(
        "mma.sync.aligned.m16n8k16.row.col.f32.bf16.bf16.f32 "
        "{%0,%1,%2,%3}, {%4,%5,%6,%7}, {%8,%9}, {%0,%1,%2,%3};"
        : "+f"(c[0]), "+f"(c[1]), "+f"(c[2]), "+f"(c[3])
        : "r"(a[0]), "r"(a[1]), "r"(a[2]), "r"(a[3]), "r"(b0), "r"(b1));
}
__device__ __forceinline__ void mma_f16(float* c, const uint32_t* a,
                                        uint32_t b0, uint32_t b1) {
    asm volatile(
        "mma.sync.aligned.m16n8k16.row.col.f32.f16.f16.f32 "
        "{%0,%1,%2,%3}, {%4,%5,%6,%7}, {%8,%9}, {%0,%1,%2,%3};"
        : "+f"(c[0]), "+f"(c[1]), "+f"(c[2]), "+f"(c[3])
        : "r"(a[0]), "r"(a[1]), "r"(a[2]), "r"(a[3]), "r"(b0), "r"(b1));
}
__device__ __forceinline__ void ldsm_x4(uint32_t* r, uint32_t addr) {
    asm volatile("ldmatrix.sync.aligned.m8n8.x4.shared.b16 {%0,%1,%2,%3}, [%4];"
                 : "=r"(r[0]), "=r"(r[1]), "=r"(r[2]), "=r"(r[3]) : "r"(addr));
}

// ---------------- layer GEMM (fp16, group-decoupled K pipelines, PDL) -------
// O = relu(A @ W^T + bias) (+ ext_next). CTA tile 32x64.
// 16 warps = 4 K-groups x (wm2 x wn2). Group q owns k in [q*256, q*256+256),
// processed as 4 chunks of 64 through a PRIVATE 3-stage pipeline synced only
// by a named barrier over the group's 128 threads (no CTA-wide sync in loop).
// Epilogue: symmetric 4-way reduction via scratch; all 16 warps store.
// B stages 0,1 and the ext tile are prefetched BEFORE griddepcontrol.wait.
#define M_TILE 32
#define N_TILE 64
#define KQ     256                // k-range per group
#define KCH    64                 // chunk width
#define NCH    4                  // chunks per group
#define GSTG   12288              // per-group stage: A 4KB + B 8KB
#define STG_B  4096
#define STAGES 3
#define SCR_OFF (STAGES * 4 * GSTG)        // 147456
#define EXT_OFF (SCR_OFF + 32768)          // 180224
#define SM_TOTAL (EXT_OFF + 8192)          // 188416
#define NTHR   512

__device__ __forceinline__ void load_A(uint32_t dst, int k0, int gtid, int m0,
    const __half* __restrict__ A)
{
    #pragma unroll
    for (int i = 0; i < 2; i++) {
        int u = gtid + (i << 7);         // 0..255 = 32 rows x 8 units
        int row = u >> 3, cu = u & 7;
        const __half* src = A + (size_t)(m0 + row) * SS + k0 + cu * 8;
        cp16(dst + row * 128 + ((cu ^ (row & 7)) << 4), src);
    }
}
__device__ __forceinline__ void load_B(uint32_t dst, int k0, int gtid, int n0,
    const __half* __restrict__ W)
{
    #pragma unroll
    for (int i = 0; i < 4; i++) {
        int u = gtid + (i << 7);         // 0..511 = 64 rows x 8 units
        int row = u >> 3, cu = u & 7;
        const __half* src = W + (size_t)(n0 + row) * SS + k0 + cu * 8;
        cp16(dst + row * 128 + ((cu ^ (row & 7)) << 4), src);
    }
}

__global__ __launch_bounds__(NTHR) void layer_kernel(
    const __half* __restrict__ A, const __half* __restrict__ W,
    const float* __restrict__ bias, const float* __restrict__ ext_next,
    __half* __restrict__ O)
{
    extern __shared__ char smem[];
    const uint32_t sb = smem_u32(smem);
    const int tid = threadIdx.x;
    const int wid = tid >> 5, lane = tid & 31;
    const int g = lane >> 2, t4 = lane & 3;
    const int q  = wid >> 2;             // K group 0..3
    const int wm = (wid >> 1) & 1;       // rows wm*16
    const int wn = wid & 1;              // cols wn*32
    const int gtid = tid & 127;
    const int m0 = blockIdx.x * M_TILE, n0 = blockIdx.y * N_TILE;
    const int kbase = q * KQ;
    const uint32_t gb = sb + q * (STAGES * GSTG);

    const int lr = lane & 7;
    const int half8 = (lane >> 3) & 1;
    const int khalf = (lane >> 4) & 1;
    const int rowA  = wm * 16 + half8 * 8 + lr;
    const int rowB0 = wn * 32 + half8 * 8 + lr;
    const int rowB1 = rowB0 + 16;
    const int swA = rowA & 7, swB0 = rowB0 & 7, swB1 = rowB1 & 7;

    // ---- prologue: weight + ext prefetch BEFORE the grid dependency ----
    load_B(gb + STG_B, kbase, gtid, n0, W);
    if (ext_next) {                       // ext tile 32x64 fp32 = 8KB, all 512 thr
        int row = tid >> 4, cu = tid & 15;
        cp16(sb + EXT_OFF + row * 256 + cu * 16,
             ext_next + (size_t)(m0 + row) * SS + n0 + cu * 4);
    }
    cp_commit();                                            // g0 = B0 (+ext)
    load_B(gb + GSTG + STG_B, kbase + KCH, gtid, n0, W);
    cp_commit();                                            // g1 = B1
    gdc_wait();                                             // prev layer done
    load_A(gb, kbase, gtid, m0, A);            cp_commit(); // g2 = A0
    load_A(gb + GSTG, kbase + KCH, gtid, m0, A); cp_commit(); // g3 = A1

    float acc[4][4] = {};

    // ---- group-private mainloop: 4 chunks, 3 stages, named-bar sync ----
    #pragma unroll
    for (int c = 0; c < NCH; c++) {
        if (c == NCH - 1) cp_wait0(); else cp_wait1();
        bar_named(q + 1);                 // group data complete + stage reusable
        if (c + 2 < NCH) {
            const uint32_t sp = gb + ((c + 2) % 3) * GSTG;
            load_A(sp, kbase + (c + 2) * KCH, gtid, m0, A);
            load_B(sp + STG_B, kbase + (c + 2) * KCH, gtid, n0, W);
            cp_commit();
        }
        const uint32_t aB = gb + (c % 3) * GSTG;
        const uint32_t bB = aB + STG_B;
        #pragma unroll
        for (int s = 0; s < 4; s++) {
            const int u = s * 2 + khalf;  // 0..7
            uint32_t ah[4], b0[4], b1[4];
            ldsm_x4(ah, aB + rowA * 128 + ((u ^ swA) << 4));
            ldsm_x4(b0, bB + rowB0 * 128 + ((u ^ swB0) << 4));
            ldsm_x4(b1, bB + rowB1 * 128 + ((u ^ swB1) << 4));
            mma_f16(acc[0], ah, b0[0], b0[2]);
            mma_f16(acc[1], ah, b0[1], b0[3]);
            mma_f16(acc[2], ah, b1[0], b1[2]);
            mma_f16(acc[3], ah, b1[1], b1[3]);
        }
    }

    // ---- symmetric 4-way reduction: warp q keeps jj=q, exchanges others ----
    const int tile = wm * 2 + wn;        // 0..3
    char* scr = smem + SCR_OFF;
    #pragma unroll
    for (int jj = 0; jj < 4; jj++) {
        if (jj != q) {
            float4* p = (float4*)(scr + (((tile * 4 + jj) * 4 + q) * 32 + lane) * 16);
            *p = make_float4(acc[jj][0], acc[jj][1], acc[jj][2], acc[jj][3]);
        }
    }
    __syncthreads();                      // only CTA-wide barrier in the kernel
    float r[4] = {acc[q][0], acc[q][1], acc[q][2], acc[q][3]};
    #pragma unroll
    for (int p = 0; p < 4; p++) {
        if (p != q) {
            float4 v = *(const float4*)(scr + (((tile * 4 + q) * 4 + p) * 32 + lane) * 16);
            r[0] += v.x; r[1] += v.y; r[2] += v.z; r[3] += v.w;
        }
    }

    // ---- epilogue: every warp handles its jj=q quadrant ----
    const int row0 = m0 + wm * 16 + g;
    const int row1 = row0 + 8;
    const int col  = n0 + wn * 32 + q * 8 + t4 * 2;
    float2 bb = *(const float2*)(bias + col);
    float v00 = fmaxf(r[0] + bb.x, 0.0f);
    float v01 = fmaxf(r[1] + bb.y, 0.0f);
    float v10 = fmaxf(r[2] + bb.x, 0.0f);
    float v11 = fmaxf(r[3] + bb.y, 0.0f);
    if (ext_next) {
        const char* eb = smem + EXT_OFF;
        const int ecol = (wn * 32 + q * 8 + t4 * 2) * 4;
        float2 e0 = *(const float2*)(eb + (wm * 16 + g) * 256 + ecol);
        float2 e1 = *(const float2*)(eb + (wm * 16 + g + 8) * 256 + ecol);
        v00 += e0.x; v01 += e0.y; v10 += e1.x; v11 += e1.y;
    }
    *(uint32_t*)(O + (size_t)row0 * SS + col) =
        (uint32_t)__half_as_ushort(__float2half_rn(v00))
        | ((uint32_t)__half_as_ushort(__float2half_rn(v01)) << 16);
    *(uint32_t*)(O + (size_t)row1 * SS + col) =
        (uint32_t)__half_as_ushort(__float2half_rn(v10))
        | ((uint32_t)__half_as_ushort(__float2half_rn(v11)) << 16);

    gdc_launch();
}

// ---------------- input projection (bf16 3-term MMA; also writes s0) --------
#define PA_HI 0
#define PA_LO 16384
#define PB_HI 32768
#define PB_LO 49152
#define P_SM  65536

#define SWU16(cu, row) ((((cu) & 8) | (((cu) & 7) ^ ((row) & 7))) << 4)

__global__ __launch_bounds__(256) void proj_mma(
    const __nv_bfloat16* __restrict__ Xh, const __nv_bfloat16* __restrict__ Xl,
    const __nv_bfloat16* __restrict__ Wh, const __nv_bfloat16* __restrict__ Wl,
    const float* __restrict__ bias, float* __restrict__ Out,
    __half* __restrict__ S0)
{
    extern __shared__ char smem[];
    const uint32_t sb = smem_u32(smem);
    const int tid = threadIdx.x;
    const int wid = tid >> 5, lane = tid & 31;
    const int g = lane >> 2, t4 = lane & 3;
    const int wm = (wid >> 1) << 4;
    const int wn = (wid & 1) << 5;
    const int m0 = blockIdx.x * 64, n0 = blockIdx.y * 64;

    #pragma unroll
    for (int i = 0; i < 16; i++) {
        int u = tid + (i << 8);
        const __nv_bfloat16* src;
        uint32_t dst;
        if (u < 2048) {
            int sel = u >> 10, v = u & 1023;
            int row = v >> 4, cu = v & 15;
            src = (sel ? Xl : Xh) + (size_t)(m0 + row) * IND + cu * 8;
            dst = sb + (sel ? PA_LO : PA_HI) + row * 256 + SWU16(cu, row);
        } else {
            int w = u - 2048;
            int sel = w >> 10, v = w & 1023;
            int row = v >> 4, cu = v & 15;
            src = (sel ? Wl : Wh) + (size_t)(n0 + row) * IND + cu * 8;
            dst = sb + (sel ? PB_LO : PB_HI) + row * 256 + SWU16(cu, row);
        }
        cp16(dst, src);
    }
    cp_commit();
    cp_wait0();
    __syncthreads();

    const int lr = lane & 7;
    const int half8 = (lane >> 3) & 1;
    const int khalf = (lane >> 4) & 1;
    const int rowA = wm + half8 * 8 + lr;
    const int rowB = wn + half8 * 8 + lr;

    float acc[4][4] = {};
    #pragma unroll
    for (int ks = 0; ks < 8; ks++) {
        const int u = ks * 2 + khalf;
        uint32_t ah[4], al[4];
        ldsm_x4(ah, sb + PA_HI + rowA * 256 + SWU16(u, rowA));
        ldsm_x4(al, sb + PA_LO + rowA * 256 + SWU16(u, rowA));
        #pragma unroll
        for (int jj = 0; jj < 2; jj++) {
            uint32_t bh[4], bl[4];
            ldsm_x4(bh, sb + PB_HI + (rowB + jj * 16) * 256 + SWU16(u, rowB + jj * 16));
            ldsm_x4(bl, sb + PB_LO + (rowB + jj * 16) * 256 + SWU16(u, rowB + jj * 16));
            mma_bf16(acc[jj * 2],     ah, bh[0], bh[2]);
            mma_bf16(acc[jj * 2],     ah, bl[0], bl[2]);
            mma_bf16(acc[jj * 2],     al, bh[0], bh[2]);
            mma_bf16(acc[jj * 2 + 1], ah, bh[1], bh[3]);
            mma_bf16(acc[jj * 2 + 1], ah, bl[1], bl[3]);
            mma_bf16(acc[jj * 2 + 1], al, bh[1], bh[3]);
        }
    }

    const int r0 = m0 + wm + g;
    const int r1 = r0 + 8;
    const int b0r = r0 >> 8, t0r = r0 & 255;
    const int b1r = r1 >> 8, t1r = r1 & 255;
    #pragma unroll
    for (int j = 0; j < 4; j++) {
        const int col = n0 + wn + j * 8 + t4 * 2;
        float2 bb = *(const float2*)(bias + col);
        float2 o0 = make_float2(acc[j][0] + bb.x, acc[j][1] + bb.y);
        float2 o1 = make_float2(acc[j][2] + bb.x, acc[j][3] + bb.y);
        *(float2*)(Out + ((size_t)t0r * BB + b0r) * SS + col) = o0;
        *(float2*)(Out + ((size_t)t1r * BB + b1r) * SS + col) = o1;
        if (t0r == 0) {
            *(uint32_t*)(S0 + (size_t)b0r * SS + col) =
                (uint32_t)__half_as_ushort(__float2half_rn(o0.x))
                | ((uint32_t)__half_as_ushort(__float2half_rn(o0.y)) << 16);
        }
    }
}

// ---------------- fused prolog: all conversions in ONE launch ----------------
#define N_W   (SS * SS / 4)
#define N_X   ((size_t)BB * TT * IND / 4)
#define N_WIN (SS * IND / 4)
#define N_TOT (2 * N_W + (int)N_X + N_WIN)

__global__ void prep_kernel(
    const float4* __restrict__ Wr1, const float4* __restrict__ Wr2,
    const float4* __restrict__ X,   const float4* __restrict__ Win,
    uint2* __restrict__ W1, uint2* __restrict__ W2,
    uint2* __restrict__ xh, uint2* __restrict__ xl,
    uint2* __restrict__ wih, uint2* __restrict__ wil)
{
    int i = blockIdx.x * blockDim.x + threadIdx.x;
    if (i >= N_TOT) return;
    if (i < 2 * N_W) {
        const float4* src = (i < N_W) ? Wr1 : Wr2;
        uint2* dst        = (i < N_W) ? W1  : W2;
        int k = (i < N_W) ? i : i - N_W;
        float4 v = src[k];
        uint2 O;
        O.x = (uint32_t)__half_as_ushort(__float2half_rn(v.x))
            | ((uint32_t)__half_as_ushort(__float2half_rn(v.y)) << 16);
        O.y = (uint32_t)__half_as_ushort(__float2half_rn(v.z))
            | ((uint32_t)__half_as_ushort(__float2half_rn(v.w)) << 16);
        dst[k] = O;
    } else {
        int k = i - 2 * N_W;
        const float4* src; uint2 *dh, *dl;
        if (k < (int)N_X) { src = X; dh = xh; dl = xl; }
        else { k -= (int)N_X; src = Win; dh = wih; dl = wil; }
        float4 v = src[k];
        __nv_bfloat16 h0 = __float2bfloat16(v.x), h1 = __float2bfloat16(v.y);
        __nv_bfloat16 h2 = __float2bfloat16(v.z), h3 = __float2bfloat16(v.w);
        __nv_bfloat16 l0 = __float2bfloat16(v.x - __bfloat162float(h0));
        __nv_bfloat16 l1 = __float2bfloat16(v.y - __bfloat162float(h1));
        __nv_bfloat16 l2 = __float2bfloat16(v.z - __bfloat162float(h2));
        __nv_bfloat16 l3 = __float2bfloat16(v.w - __bfloat162float(h3));
        uint2 H, L;
        H.x = (uint32_t)__bfloat16_as_ushort(h0) | ((uint32_t)__bfloat16_as_ushort(h1) << 16);
        H.y = (uint32_t)__bfloat16_as_ushort(h2) | ((uint32_t)__bfloat16_as_ushort(h3) << 16);
        L.x = (uint32_t)__bfloat16_as_ushort(l0) | ((uint32_t)__bfloat16_as_ushort(l1) << 16);
        L.y = (uint32_t)__bfloat16_as_ushort(l2) | ((uint32_t)__bfloat16_as_ushort(l3) << 16);
        dh[k] = H; dl[k] = L;
    }
}

// ---------------- broadcast final state (fp16 -> fp32, all timesteps) -------
__global__ void bcastH_kernel(const uint2* __restrict__ s, float4* __restrict__ out)
{
    int i = blockIdx.x * blockDim.x + threadIdx.x;
    int b  = i >> 16;
    int s4 = i & 255;
    uint2 H = s[(b << 8) + s4];
    float4 o;
    o.x = __half2float(__ushort_as_half((unsigned short)(H.x & 0xFFFF)));
    o.y = __half2float(__ushort_as_half((unsigned short)(H.x >> 16)));
    o.z = __half2float(__ushort_as_half((unsigned short)(H.y & 0xFFFF)));
    o.w = __half2float(__ushort_as_half((unsigned short)(H.y >> 16)));
    out[i] = o;
}

// ---------------- driver ----------------------------------------------------
extern "C" void kernel_launch(void* const* d_in, const int* in_sizes, int n_in,
                              void* d_out, int out_size)
{
    const float* x      = (const float*)d_in[0];
    const float* W_in   = (const float*)d_in[1];
    const float* b_in   = (const float*)d_in[2];
    const float* W_rec  = (const float*)d_in[3];
    const float* b_rec  = (const float*)d_in[4];
    const float* W_rec2 = (const float*)d_in[5];
    const float* b_rec2 = (const float*)d_in[6];
    float* out = (float*)d_out;

    float* ext;
    __half *sA, *sB, *W1, *W2;
    __nv_bfloat16 *xh, *xl, *Winh, *Winl;
    cudaGetSymbolAddress((void**)&ext, g_ext);
    cudaGetSymbolAddress((void**)&sA,  g_sA);
    cudaGetSymbolAddress((void**)&sB,  g_sB);
    cudaGetSymbolAddress((void**)&W1,  g_W1);
    cudaGetSymbolAddress((void**)&W2,  g_W2);
    cudaGetSymbolAddress((void**)&xh,  g_xh);
    cudaGetSymbolAddress((void**)&xl,  g_xl);
    cudaGetSymbolAddress((void**)&Winh, g_Winh);
    cudaGetSymbolAddress((void**)&Winl, g_Winl);

    cudaFuncSetAttribute(layer_kernel, cudaFuncAttributeMaxDynamicSharedMemorySize, SM_TOTAL);
    cudaFuncSetAttribute(proj_mma,     cudaFuncAttributeMaxDynamicSharedMemorySize, P_SM);

    // Launch 0: fused prolog
    prep_kernel<<<(N_TOT + 255) / 256, 256>>>(
        (const float4*)W_rec, (const float4*)W_rec2,
        (const float4*)x, (const float4*)W_in,
        (uint2*)W1, (uint2*)W2, (uint2*)xh, (uint2*)xl, (uint2*)Winh, (uint2*)Winl);

    // Launch 1: ext = x @ W_in^T + b_in; also writes s0 = ext[0] fp16
    {
        dim3 grid((BB * TT) / 64, SS / 64);
        proj_mma<<<grid, 256, P_SM>>>(xh, xl, Winh, Winl, b_in, ext, sA);
    }

    // Launches 2..513: scan, PDL-chained
    {
        cudaLaunchConfig_t cfg = {};
        cfg.gridDim  = dim3(BB / M_TILE, SS / N_TILE, 1);   // (8, 16) = 128 CTAs
        cfg.blockDim = dim3(NTHR, 1, 1);
        cfg.dynamicSmemBytes = SM_TOTAL;
        cudaLaunchAttribute at[1];
        at[0].id = cudaLaunchAttributeProgrammaticStreamSerialization;
        at[0].val.programmaticStreamSerializationAllowed = 1;
        cfg.attrs = at;
        cfg.numAttrs = 1;

        const float* nil = nullptr;
        for (int t = 0; t < TT; t++) {
            if (cudaLaunchKernelEx(&cfg, layer_kernel,
                    (const __half*)sA, (const __half*)W1,
                    (const float*)b_rec, nil, sB) != cudaSuccess)
                layer_kernel<<<cfg.gridDim, cfg.blockDim, SM_TOTAL>>>(
                    sA, W1, b_rec, nullptr, sB);
            const float* en = (t + 1 < TT) ? ext + (size_t)(t + 1) * BB * SS : nullptr;
            if (cudaLaunchKernelEx(&cfg, layer_kernel,
                    (const __half*)sB, (const __half*)W2,
                    (const float*)b_rec2, en, sA) != cudaSuccess)
                layer_kernel<<<cfg.gridDim, cfg.blockDim, SM_TOTAL>>>(
                    sB, W2, b_rec2, en, sA);
        }
    }

    // Final: broadcast final state
    bcastH_kernel<<<(BB * TT * SS / 4) / 256, 256>>>((const uint2*)sA, (float4*)out);
}